// round 9
// baseline (speedup 1.0000x reference)
#include <cuda_runtime.h>
#include <cstdint>
#include <math.h>

#define QLEN  1024
#define KLEN  1024
#define RLEN  2048
#define NPRED 256
#define BSZ   4
#define NH    16
#define DH    64
#define DM    1024
#define DI    4096
#define NB    (BSZ*NH)   /* 64 head-batches */

typedef unsigned int u32;

// ---------------------------------------------------------------------------
// Scratch (device globals; allocation in kernel_launch is forbidden)
// ---------------------------------------------------------------------------
__device__ float g_KH [QLEN*BSZ*DM];
__device__ float g_VH [QLEN*BSZ*DM];
__device__ float g_KR [RLEN*BSZ*DM];
__device__ float g_QT [QLEN*BSZ*DM];
__device__ float g_QW [QLEN*BSZ*DM];
__device__ float g_QR [QLEN*BSZ*DM];
__device__ float g_QG [NPRED*BSZ*DM];
__device__ float g_AC [(long)NB*QLEN*KLEN];
__device__ float g_BD [(long)NB*QLEN*KLEN];   // compact shifted scores (masked)
__device__ float g_AV [QLEN*BSZ*DM];
__device__ float g_AV2[NPRED*BSZ*DM];
__device__ float g_ATTH[QLEN*BSZ*DM];
__device__ float g_ATTG[NPRED*BSZ*DM];
__device__ float g_FF1[QLEN*BSZ*DI];
__device__ float g_FF2[QLEN*BSZ*DM];

// ---------------------------------------------------------------------------
__device__ __forceinline__ u32 f2tf32(float v)
{
    u32 r;
    asm("cvt.rna.tf32.f32 %0, %1;" : "=r"(r) : "f"(v));
    return r;
}
__device__ __forceinline__ u32 cvtu(u32 raw)
{
    u32 r;
    asm("cvt.rna.tf32.f32 %0, %1;" : "=r"(r) : "f"(__uint_as_float(raw)));
    return r;
}
__device__ __forceinline__ float tf32r(float v)
{
    return __uint_as_float(f2tf32(v));
}

__device__ __forceinline__ void mma_tf32(float* c, const u32* a, const u32* b)
{
    asm volatile(
        "mma.sync.aligned.m16n8k8.row.col.f32.tf32.tf32.f32 "
        "{%0,%1,%2,%3}, {%4,%5,%6,%7}, {%8,%9}, {%0,%1,%2,%3};\n"
        : "+f"(c[0]), "+f"(c[1]), "+f"(c[2]), "+f"(c[3])
        : "r"(a[0]), "r"(a[1]), "r"(a[2]), "r"(a[3]), "r"(b[0]), "r"(b[1]));
}

__device__ __forceinline__ void ldsm4(u32& r0, u32& r1, u32& r2, u32& r3, u32 addr)
{
    asm volatile(
        "ldmatrix.sync.aligned.m8n8.x4.shared.b16 {%0,%1,%2,%3}, [%4];\n"
        : "=r"(r0), "=r"(r1), "=r"(r2), "=r"(r3) : "r"(addr));
}

__device__ __forceinline__ void cpa16(u32 saddr, const void* gaddr)
{
    asm volatile("cp.async.cg.shared.global [%0], [%1], 16;\n"
                 :: "r"(saddr), "l"(gaddr));
}
__device__ __forceinline__ void cpa_commit() { asm volatile("cp.async.commit_group;\n"); }
__device__ __forceinline__ void cpa_wait1()  { asm volatile("cp.async.wait_group 1;\n"); }

// ===========================================================================
// FAST GEMM. A k-contiguous, M%128==0, K%16==0, N%TBN==0.
//   BTR=1: B n-contiguous. BTR=0: B k-contiguous.
//   CVA/CVB: tf32-convert at fragment load.
//   SHIFT=1: BD epilogue — scatter row-shifted (j=col+row-1024) into a
//            1024-wide buffer with the attention mask folded in.
// 3-stage cp.async pipeline, 128 x TBN tile, 256 threads.
// ===========================================================================
#define SK 20   /* A / B(ldsm) smem row stride in u32 */

template<int TBN, int BTR, int CVA, int CVB, int SHIFT>
__global__ __launch_bounds__(256, 2) void gemm_fast(
    const float* __restrict__ A, const float* __restrict__ B,
    float* __restrict__ C, int K,
    long ldaI, long bsA,
    long ldb,  long bsB,
    long ldcI, long bsC,
    const float* __restrict__ bias, int act, int diagskip, int rndC,
    float* __restrict__ C2, const float* __restrict__ bias2,
    const float* __restrict__ smask)
{
    constexpr int WARPS_M = (TBN == 128) ? 2 : 4;
    constexpr int MT      = (128 / WARPS_M) / 16;     // 4 / 2
    constexpr int NT      = 4;
    constexpr int NCHB    = TBN / 64;
    constexpr int BSTR    = BTR ? (TBN + 8) : SK;
    constexpr int ABUF    = 128 * SK * 4;
    constexpr int BBUF    = (BTR ? 16 * BSTR : TBN * SK) * 4;

    extern __shared__ __align__(16) u32 dyn[];
    u32* Asp = dyn;
    u32* Bsp = dyn + 3 * 128 * SK;

    const int i0 = blockIdx.y * 128;
    const int j0 = blockIdx.x * TBN;
    if (diagskip && (i0 + j0 < 770 || i0 + j0 > 2047)) return;

    const int z = blockIdx.z;
    const float* Ab = A + (long)z * bsA;
    const float* Bb = B + (long)z * bsB;
    float*       Cb = C + (long)z * bsC;

    const int tid  = threadIdx.x;
    const int warp = tid >> 5;
    const int lane = tid & 31;
    const int g = lane >> 2;
    const int t = lane & 3;
    const int wm = (warp % WARPS_M) * (128 / WARPS_M);
    const int wn = (warp / WARPS_M) * 32;

    const u32 sa_base = (u32)__cvta_generic_to_shared(Asp);
    const u32 sb_base = (u32)__cvta_generic_to_shared(Bsp);

    const int mi = lane >> 3;
    const int ri = lane & 7;
    u32 aoff[MT];
#pragma unroll
    for (int mt = 0; mt < MT; mt++)
        aoff[mt] = ((u32)(wm + mt * 16 + (mi & 1) * 8 + ri) * SK + (u32)(mi >> 1) * 4) * 4;
    u32 boff[2];
#pragma unroll
    for (int p = 0; p < 2; p++)
        boff[p] = ((u32)(wn + p * 16 + (mi >> 1) * 8 + ri) * SK + (u32)(mi & 1) * 4) * 4;

    const int arow = tid >> 2;
    const int aq4  = (tid & 3) * 4;
    u32 sAo[2];
    const float* gA[2];
    sAo[0] = ((u32)arow * SK + aq4) * 4;
    sAo[1] = ((u32)(arow + 64) * SK + aq4) * 4;
    gA[0] = Ab + (long)(i0 + arow) * ldaI + aq4;
    gA[1] = Ab + (long)(i0 + arow + 64) * ldaI + aq4;

    u32 sBo[NCHB];
    const float* gB[NCHB];
    long bstep;
    if (BTR) {
        bstep = 16 * ldb;
#pragma unroll
        for (int u = 0; u < NCHB; u++) {
            int idx = tid + 256 * u;
            int k  = idx / (TBN / 4);
            int n4 = (idx % (TBN / 4)) * 4;
            sBo[u] = ((u32)k * BSTR + n4) * 4;
            gB[u]  = Bb + (long)k * ldb + (j0 + n4);
        }
    } else {
        bstep = 16;
#pragma unroll
        for (int u = 0; u < NCHB; u++) {
            int idx = tid + 256 * u;
            int n  = idx >> 2;
            int q4 = (idx & 3) * 4;
            sBo[u] = ((u32)n * SK + q4) * 4;
            gB[u]  = Bb + (long)(j0 + n) * ldb + q4;
        }
    }

    const int nk = K >> 4;

    auto issue = [&](int stage, int it) {
        u32 ab = sa_base + (u32)stage * ABUF;
        u32 bb = sb_base + (u32)stage * BBUF;
        long ka = (long)it * 16;
        long kb = (long)it * bstep;
        cpa16(ab + sAo[0], gA[0] + ka);
        cpa16(ab + sAo[1], gA[1] + ka);
#pragma unroll
        for (int u = 0; u < NCHB; u++)
            cpa16(bb + sBo[u], gB[u] + kb);
    };

    float acc[MT][NT][4];
#pragma unroll
    for (int mt = 0; mt < MT; mt++)
#pragma unroll
        for (int nt = 0; nt < NT; nt++)
#pragma unroll
            for (int e = 0; e < 4; e++) acc[mt][nt][e] = 0.0f;

    issue(0, 0); cpa_commit();
    if (nk > 1) issue(1, 1);
    cpa_commit();

    int buf = 0;
    for (int it = 0; it < nk; it++) {
        cpa_wait1();
        __syncthreads();

        const u32 ab = sa_base + (u32)buf * ABUF;
        const u32 bb = sb_base + (u32)buf * BBUF;
        const u32* Brow = Bsp + buf * (BBUF / 4);

#pragma unroll
        for (int kk = 0; kk < 2; kk++) {
            const u32 ksb = kk * 32;
            const int ks  = kk * 8;
            u32 af[MT][4], bf2[2][4];
#pragma unroll
            for (int mt = 0; mt < MT; mt++) {
                ldsm4(af[mt][0], af[mt][1], af[mt][2], af[mt][3], ab + aoff[mt] + ksb);
                if (CVA) {
                    af[mt][0] = cvtu(af[mt][0]); af[mt][1] = cvtu(af[mt][1]);
                    af[mt][2] = cvtu(af[mt][2]); af[mt][3] = cvtu(af[mt][3]);
                }
            }
            if (BTR) {
#pragma unroll
                for (int p = 0; p < 2; p++) {
                    int c = wn + p * 16;
                    bf2[p][0] = Brow[(ks + t) * BSTR + c + g];
                    bf2[p][1] = Brow[(ks + t + 4) * BSTR + c + g];
                    bf2[p][2] = Brow[(ks + t) * BSTR + c + 8 + g];
                    bf2[p][3] = Brow[(ks + t + 4) * BSTR + c + 8 + g];
                    if (CVB) {
                        bf2[p][0] = cvtu(bf2[p][0]); bf2[p][1] = cvtu(bf2[p][1]);
                        bf2[p][2] = cvtu(bf2[p][2]); bf2[p][3] = cvtu(bf2[p][3]);
                    }
                }
            } else {
#pragma unroll
                for (int p = 0; p < 2; p++) {
                    ldsm4(bf2[p][0], bf2[p][1], bf2[p][2], bf2[p][3], bb + boff[p] + ksb);
                    if (CVB) {
                        bf2[p][0] = cvtu(bf2[p][0]); bf2[p][1] = cvtu(bf2[p][1]);
                        bf2[p][2] = cvtu(bf2[p][2]); bf2[p][3] = cvtu(bf2[p][3]);
                    }
                }
            }
#pragma unroll
            for (int mt = 0; mt < MT; mt++)
#pragma unroll
                for (int nt = 0; nt < NT; nt++)
                    mma_tf32(acc[mt][nt], af[mt], &bf2[nt >> 1][(nt & 1) * 2]);
        }

        int ns = it + 2;
        if (ns < nk) issue(ns >= 3 ? ns - 3 * (ns / 3) : ns, ns);
        cpa_commit();
        buf = (buf == 2) ? 0 : buf + 1;
    }

    if (SHIFT) {
        // scatter: BDs[i][j] = acc - 8e30*mask[i][j][b],  j = col + i - 1024
        const int b = z >> 4;
#pragma unroll
        for (int mt = 0; mt < MT; mt++)
#pragma unroll
            for (int nt = 0; nt < NT; nt++) {
                int col = j0 + wn + nt * 8 + t * 2;
#pragma unroll
                for (int half = 0; half < 2; half++) {
                    int row = i0 + wm + mt * 16 + g + half * 8;
#pragma unroll
                    for (int e2 = 0; e2 < 2; e2++) {
                        int j = col + e2 + row - 1024;
                        if (j >= 0 && j < 1024) {
                            float v = acc[mt][nt][half * 2 + e2]
                                    - 8e30f * smask[((long)row * 1024 + j) * 4 + b];
                            Cb[(long)row * ldcI + j] = v;
                        }
                    }
                }
            }
        return;
    }

    // normal epilogue
#pragma unroll
    for (int mt = 0; mt < MT; mt++) {
#pragma unroll
        for (int nt = 0; nt < NT; nt++) {
            int col = j0 + wn + nt * 8 + t * 2;
            float b0 = 0.0f, b1 = 0.0f;
            if (bias) { b0 = bias[col]; b1 = bias[col + 1]; }
            float c0 = 0.0f, c1 = 0.0f;
            if (C2) { c0 = bias2[col]; c1 = bias2[col + 1]; }
#pragma unroll
            for (int half = 0; half < 2; half++) {
                int row = i0 + wm + mt * 16 + g + half * 8;
                float a0 = acc[mt][nt][half * 2 + 0];
                float a1 = acc[mt][nt][half * 2 + 1];
                float v0 = a0 + b0, v1 = a1 + b1;
                if (act) {
                    v0 = 0.5f * v0 * (1.0f + erff(v0 * 0.70710678118654752f));
                    v1 = 0.5f * v1 * (1.0f + erff(v1 * 0.70710678118654752f));
                }
                if (rndC) { v0 = tf32r(v0); v1 = tf32r(v1); }
                *(float2*)&Cb[(long)row * ldcI + col] = make_float2(v0, v1);
                if (C2) {
                    float w0 = a0 + c0, w1 = a1 + c1;
                    if (rndC) { w0 = tf32r(w0); w1 = tf32r(w1); }
                    *(float2*)&C2[(long)row * ldcI + col] = make_float2(w0, w1);
                }
            }
        }
    }
}

// ===========================================================================
// Fused softmax + P@V (flash-style, un-normalized accumulate, scale by 1/L).
// Block: 128 q-rows (blockIdx.x) x one head z (blockIdx.y); output 128x64.
// S = (AC + BDS)*0.125 streamed; P never hits DRAM.
// ===========================================================================
__global__ __launch_bounds__(256, 2) void attn_pv(
    const float* __restrict__ AC, const float* __restrict__ BDS,
    const float* __restrict__ VH, float* __restrict__ O)
{
    constexpr int SKC = 20;
    constexpr int SCH = 128 * SKC;   // words per S-chunk buffer
    constexpr int VCH = 16 * 72;     // words per V-chunk buffer

    extern __shared__ __align__(16) float dynf[];
    float* Sac = dynf;                       // [3][SCH]
    float* Sbd = Sac + 3 * SCH;              // [3][SCH]
    float* Vb  = Sbd + 3 * SCH;              // [3][VCH]
    u32*   Ap  = (u32*)(Vb + 3 * VCH);       // [2][SCH]
    float* rowM   = (float*)(Ap + 2 * SCH);  // [128]
    float* rowInv = rowM + 128;              // [128]
    float* red    = rowInv + 128;            // [256]

    const int i0g = blockIdx.x * 128;
    const int z   = blockIdx.y;

    const int tid  = threadIdx.x;
    const int warp = tid >> 5;
    const int lane = tid & 31;
    const int g = lane >> 2;
    const int t = lane & 3;
    const int wm = (warp & 3) * 32;   // 4 M-warps
    const int wn = (warp >> 2) * 32;  // 2 N-warps

    const float* acB = AC  + ((long)z * QLEN + i0g) * 1024;
    const float* bdB = BDS + ((long)z * QLEN + i0g) * 1024;
    const float* vB  = VH  + (long)z * 64;

    const u32 sac = (u32)__cvta_generic_to_shared(Sac);
    const u32 sbd = (u32)__cvta_generic_to_shared(Sbd);
    const u32 svb = (u32)__cvta_generic_to_shared(Vb);
    const u32 sap = (u32)__cvta_generic_to_shared(Ap);

    const int r2 = tid >> 2, q2 = (tid & 3) * 4;   // AC/BD staging
    const int rv = tid >> 4, qv = (tid & 15) * 4;  // V staging

    auto issue = [&](int stage, int it) {
        const int c0 = it * 16;
        u32 oa = sac + (u32)(stage * SCH) * 4;
        u32 ob = sbd + (u32)(stage * SCH) * 4;
        u32 ov = svb + (u32)(stage * VCH) * 4;
        cpa16(oa + ((u32)r2 * SKC + q2) * 4,        acB + (long)r2 * 1024 + c0 + q2);
        cpa16(oa + ((u32)(r2 + 64) * SKC + q2) * 4, acB + (long)(r2 + 64) * 1024 + c0 + q2);
        cpa16(ob + ((u32)r2 * SKC + q2) * 4,        bdB + (long)r2 * 1024 + c0 + q2);
        cpa16(ob + ((u32)(r2 + 64) * SKC + q2) * 4, bdB + (long)(r2 + 64) * 1024 + c0 + q2);
        cpa16(ov + ((u32)rv * 72 + qv) * 4,         vB + (long)(c0 + rv) * 4096 + qv);
    };

    // prologue (overlaps with phase 1)
    issue(0, 0); cpa_commit();
    issue(1, 1); cpa_commit();

    // ---------------- phase 1: row max ----------------
    const int prow  = tid >> 1;
    const int phalf = tid & 1;
    {
        const float4* a4 = (const float4*)(acB + (long)prow * 1024 + phalf * 512);
        const float4* b4 = (const float4*)(bdB + (long)prow * 1024 + phalf * 512);
        float m = -1e38f;
#pragma unroll 4
        for (int u = 0; u < 128; u++) {
            float4 a = a4[u], b = b4[u];
            m = fmaxf(m, fmaxf(fmaxf(a.x + b.x, a.y + b.y),
                               fmaxf(a.z + b.z, a.w + b.w)));
        }
        red[tid] = m;
    }
    __syncthreads();
    if (phalf == 0)
        rowM[prow] = fmaxf(red[tid], red[tid + 1]) * 0.125f;
    __syncthreads();
    const float Ms = rowM[prow];

    // LDSM A-fragment offsets (MT=2)
    const int mi = lane >> 3, ri = lane & 7;
    u32 aoff[2];
#pragma unroll
    for (int mt = 0; mt < 2; mt++)
        aoff[mt] = ((u32)(wm + mt * 16 + (mi & 1) * 8 + ri) * SKC + (u32)(mi >> 1) * 4) * 4;

    float acc[2][4][4];
#pragma unroll
    for (int mt = 0; mt < 2; mt++)
#pragma unroll
        for (int nt = 0; nt < 4; nt++)
#pragma unroll
            for (int e = 0; e < 4; e++) acc[mt][nt][e] = 0.0f;

    float lsum = 0.0f;
    const int cbase = prow * SKC + phalf * 8;

    int buf = 0;
    for (int it = 0; it < 64; it++) {
        cpa_wait1();
        __syncthreads();

        // convert: e = exp(s - M) -> tf32 into Ap[it&1]; accumulate L
        {
            const float* sa = Sac + buf * SCH + cbase;
            const float* sb = Sbd + buf * SCH + cbase;
            u32* pa = Ap + (it & 1) * SCH + cbase;
            float4 a0 = *(const float4*)sa, a1 = *(const float4*)(sa + 4);
            float4 b0 = *(const float4*)sb, b1 = *(const float4*)(sb + 4);
            float e0 = __expf((a0.x + b0.x) * 0.125f - Ms);
            float e1 = __expf((a0.y + b0.y) * 0.125f - Ms);
            float e2 = __expf((a0.z + b0.z) * 0.125f - Ms);
            float e3 = __expf((a0.w + b0.w) * 0.125f - Ms);
            float e4 = __expf((a1.x + b1.x) * 0.125f - Ms);
            float e5 = __expf((a1.y + b1.y) * 0.125f - Ms);
            float e6 = __expf((a1.z + b1.z) * 0.125f - Ms);
            float e7 = __expf((a1.w + b1.w) * 0.125f - Ms);
            lsum += ((e0 + e1) + (e2 + e3)) + ((e4 + e5) + (e6 + e7));
            uint4 w0 = make_uint4(f2tf32(e0), f2tf32(e1), f2tf32(e2), f2tf32(e3));
            uint4 w1 = make_uint4(f2tf32(e4), f2tf32(e5), f2tf32(e6), f2tf32(e7));
            *(uint4*)pa = w0;
            *(uint4*)(pa + 4) = w1;
        }
        __syncthreads();

        const u32 apb = sap + (u32)((it & 1) * SCH) * 4;
        const float* Brow = Vb + buf * VCH;
#pragma unroll
        for (int kk = 0; kk < 2; kk++) {
            const u32 ksb = kk * 32;
            const int ks  = kk * 8;
            u32 af[2][4], bf2[2][4];
#pragma unroll
            for (int mt = 0; mt < 2; mt++)
                ldsm4(af[mt][0], af[mt][1], af[mt][2], af[mt][3], apb + aoff[mt] + ksb);
#pragma unroll
            for (int p = 0; p < 2; p++) {
                int c = wn + p * 16;
                bf2[p][0] = __float_as_uint(Brow[(ks + t) * 72 + c + g]);
                bf2[p][1] = __float_as_uint(Brow[(ks + t + 4) * 72 + c + g]);
                bf2[p][2] = __float_as_uint(Brow[(ks + t) * 72 + c + 8 + g]);
                bf2[p][3] = __float_as_uint(Brow[(ks + t + 4) * 72 + c + 8 + g]);
            }
#pragma unroll
            for (int mt = 0; mt < 2; mt++)
#pragma unroll
                for (int nt = 0; nt < 4; nt++)
                    mma_tf32(acc[mt][nt], af[mt], &bf2[nt >> 1][(nt & 1) * 2]);
        }

        int ns = it + 2;
        if (ns < 64) issue(ns % 3, ns);
        cpa_commit();
        buf = (buf == 2) ? 0 : buf + 1;
    }

    // L reduction (each thread owned one row half across all chunks)
    red[tid] = lsum;
    __syncthreads();
    if (phalf == 0)
        rowInv[prow] = 1.0f / (red[tid] + red[tid + 1]);
    __syncthreads();

    // epilogue: O = acc / L
    float* Ob = O + (long)z * 64;
#pragma unroll
    for (int mt = 0; mt < 2; mt++)
#pragma unroll
        for (int nt = 0; nt < 4; nt++) {
            int col = wn + nt * 8 + t * 2;
#pragma unroll
            for (int half = 0; half < 2; half++) {
                int rl = wm + mt * 16 + g + half * 8;
                float inv = rowInv[rl];
                float v0 = acc[mt][nt][half * 2 + 0] * inv;
                float v1 = acc[mt][nt][half * 2 + 1] * inv;
                *(float2*)&Ob[(long)(i0g + rl) * 4096 + col] = make_float2(v0, v1);
            }
        }
}

// ===========================================================================
// Generic fallback — used only for the two target-mapping GEMMs.
// ===========================================================================
#define BM 128
#define BN 64
#define BKT 16

__global__ __launch_bounds__(256) void bgemm_tc(
    const float* __restrict__ A, const float* __restrict__ B,
    float* __restrict__ C,
    int M, int N, int K,
    long ldaI, long ldaK, long bsA,
    long ldbK, long ldbJ, long bsB,
    long ldcI, long bsC)
{
    __shared__ u32 As[2][BM][BKT + 1];
    __shared__ u32 Bs[2][BN][BKT + 1];

    const int z = blockIdx.z;
    const float* Ab = A + (long)z * bsA;
    const float* Bb = B + (long)z * bsB;
    float*       Cb = C + (long)z * bsC;

    const int i0 = blockIdx.y * BM;
    const int j0 = blockIdx.x * BN;
    const int tid  = threadIdx.x;
    const int warp = tid >> 5;
    const int lane = tid & 31;
    const int g = lane >> 2;
    const int t = lane & 3;
    const int wm = (warp & 3) * 32;
    const int wn = (warp >> 2) * 32;

    const bool ak1 = (ldaK == 1);
    const bool bj1 = (ldbJ == 1);

    float acc[2][4][4];
#pragma unroll
    for (int mt = 0; mt < 2; mt++)
#pragma unroll
        for (int nt = 0; nt < 4; nt++)
#pragma unroll
            for (int e = 0; e < 4; e++) acc[mt][nt][e] = 0.0f;

    float ra[8], rb[4];

    auto stage = [&](int k0) {
#pragma unroll
        for (int u = 0; u < 8; u++) {
            int e = tid + u * 256;
            int i, k;
            if (ak1) { k = e & 15; i = e >> 4; }
            else     { i = e & 127; k = e >> 7; }
            int gi = i0 + i, gk = k0 + k;
            ra[u] = (gi < M && gk < K) ? Ab[(long)gi * ldaI + (long)gk * ldaK] : 0.0f;
        }
#pragma unroll
        for (int u = 0; u < 4; u++) {
            int e = tid + u * 256;
            int n, k;
            if (bj1) { n = e & 63; k = e >> 6; }
            else     { k = e & 15; n = e >> 4; }
            int gn = j0 + n, gk = k0 + k;
            rb[u] = (gn < N && gk < K) ? Bb[(long)gk * ldbK + (long)gn * ldbJ] : 0.0f;
        }
    };
    auto commit = [&](int buf) {
#pragma unroll
        for (int u = 0; u < 8; u++) {
            int e = tid + u * 256;
            int i, k;
            if (ak1) { k = e & 15; i = e >> 4; }
            else     { i = e & 127; k = e >> 7; }
            As[buf][i][k] = f2tf32(ra[u]);
        }
#pragma unroll
        for (int u = 0; u < 4; u++) {
            int e = tid + u * 256;
            int n, k;
            if (bj1) { n = e & 63; k = e >> 6; }
            else     { k = e & 15; n = e >> 4; }
            Bs[buf][n][k] = f2tf32(rb[u]);
        }
    };

    stage(0);
    commit(0);
    __syncthreads();

    int buf = 0;
    for (int k0 = 0; k0 < K; k0 += BKT) {
        const bool more = (k0 + BKT) < K;
        if (more) stage(k0 + BKT);

#pragma unroll
        for (int kk = 0; kk < 2; kk++) {
            const int ks = kk * 8;
            u32 af[2][4], bf[4][2];
#pragma unroll
            for (int mt = 0; mt < 2; mt++) {
                int r = wm + mt * 16;
                af[mt][0] = As[buf][r + g    ][ks + t];
                af[mt][1] = As[buf][r + g + 8][ks + t];
                af[mt][2] = As[buf][r + g    ][ks + t + 4];
                af[mt][3] = As[buf][r + g + 8][ks + t + 4];
            }
#pragma unroll
            for (int nt = 0; nt < 4; nt++) {
                int c = wn + nt * 8;
                bf[nt][0] = Bs[buf][c + g][ks + t];
                bf[nt][1] = Bs[buf][c + g][ks + t + 4];
            }
#pragma unroll
            for (int mt = 0; mt < 2; mt++)
#pragma unroll
                for (int nt = 0; nt < 4; nt++)
                    mma_tf32(acc[mt][nt], af[mt], bf[nt]);
        }

        if (more) {
            commit(buf ^ 1);
            __syncthreads();
            buf ^= 1;
        }
    }

#pragma unroll
    for (int mt = 0; mt < 2; mt++) {
#pragma unroll
        for (int nt = 0; nt < 4; nt++) {
            int col = j0 + wn + nt * 8 + t * 2;
            if (col >= N) continue;
#pragma unroll
            for (int half = 0; half < 2; half++) {
                int row = i0 + wm + mt * 16 + g + half * 8;
                if (row >= M) continue;
                *(float2*)&Cb[(long)row * ldcI + col] =
                    make_float2(acc[mt][nt][half * 2 + 0], acc[mt][nt][half * 2 + 1]);
            }
        }
    }
}

// ---------------------------------------------------------------------------
__global__ void add_bias2(const float* __restrict__ src,
                          const float* __restrict__ bw,
                          const float* __restrict__ br,
                          float* __restrict__ dw, float* __restrict__ dr, long n)
{
    long idx = (long)blockIdx.x * blockDim.x + threadIdx.x;
    long stride = (long)gridDim.x * blockDim.x;
    for (; idx < n; idx += stride) {
        int c = (int)(idx & (DM - 1));
        float v = src[idx];
        dw[idx] = tf32r(v + bw[c]);
        dr[idx] = tf32r(v + br[c]);
    }
}

// ---------------------------------------------------------------------------
__global__ void ln_res(const float* __restrict__ x, const float* __restrict__ res,
                       const float* __restrict__ sc, const float* __restrict__ bi,
                       float* __restrict__ out)
{
    const long row = blockIdx.x;
    const float* xr = x   + row * DM;
    const float* rr = res + row * DM;
    float*       o  = out + row * DM;
    const int tid = threadIdx.x;

    __shared__ float red[256];

    float v[4];
    float s = 0.0f;
#pragma unroll
    for (int r = 0; r < 4; r++) {
        int c = tid + r * 256;
        v[r] = xr[c] + rr[c];
        s += v[r];
    }
    red[tid] = s; __syncthreads();
    for (int st = 128; st > 0; st >>= 1) {
        if (tid < st) red[tid] += red[tid + st];
        __syncthreads();
    }
    float mean = red[0] * (1.0f / DM); __syncthreads();

    float sq = 0.0f;
#pragma unroll
    for (int r = 0; r < 4; r++) {
        float d = v[r] - mean;
        sq += d * d;
    }
    red[tid] = sq; __syncthreads();
    for (int st = 128; st > 0; st >>= 1) {
        if (tid < st) red[tid] += red[tid + st];
        __syncthreads();
    }
    float rstd = rsqrtf(red[0] * (1.0f / DM) + 1e-8f);
#pragma unroll
    for (int r = 0; r < 4; r++) {
        int c = tid + r * 256;
        o[c] = (v[r] - mean) * rstd * sc[c] + bi[c];
    }
}

// ---------------------------------------------------------------------------
template<int TBN, int BTR, int CVA, int CVB, int SHIFT = 0>
static void launchG(const float* A, const float* B, float* C,
                    int M, int N, int K,
                    long ldaI, long bsA, long ldb, long bsB,
                    long ldcI, long bsC,
                    const float* bias, int act, int nb,
                    int diagskip = 0, int rndC = 0,
                    float* C2 = nullptr, const float* bias2 = nullptr,
                    const float* smask = nullptr)
{
    constexpr int BSTR = BTR ? (TBN + 8) : SK;
    constexpr int SMEM = (3 * 128 * SK + 3 * (BTR ? 16 * BSTR : TBN * SK)) * 4;
    cudaFuncSetAttribute(gemm_fast<TBN, BTR, CVA, CVB, SHIFT>,
                         cudaFuncAttributeMaxDynamicSharedMemorySize, SMEM);
    gemm_fast<TBN, BTR, CVA, CVB, SHIFT><<<dim3(N / TBN, M / 128, nb), 256, SMEM>>>(
        A, B, C, K, ldaI, bsA, ldb, bsB, ldcI, bsC, bias, act, diagskip, rndC,
        C2, bias2, smask);
}

extern "C" void kernel_launch(void* const* d_in, const int* in_sizes, int n_in,
                              void* d_out, int out_size)
{
    const float* Xh  = (const float*)d_in[0];
    const float* Xg  = (const float*)d_in[1];
    const float* mh  = (const float*)d_in[2];
    const float* mg  = (const float*)d_in[3];
    const float* R   = (const float*)d_in[4];
    const float* TM  = (const float*)d_in[5];
    const float* qw  = (const float*)d_in[6];
    const float* kw  = (const float*)d_in[7];
    const float* vw  = (const float*)d_in[8];
    const float* rw  = (const float*)d_in[9];
    const float* rrb = (const float*)d_in[10];
    const float* rwb = (const float*)d_in[11];
    const float* lns = (const float*)d_in[12];
    const float* lnb = (const float*)d_in[13];
    const float* w1  = (const float*)d_in[14];
    const float* b1  = (const float*)d_in[15];
    const float* w2  = (const float*)d_in[16];
    const float* b2  = (const float*)d_in[17];
    const float* fls = (const float*)d_in[18];
    const float* flb = (const float*)d_in[19];
    float* out = (float*)d_out;

    float *KH, *VH, *KR, *QT, *QW, *QR, *QG, *AC, *BD, *AV, *AV2,
          *ATTH, *ATTG, *FF1, *FF2;
    cudaGetSymbolAddress((void**)&KH,  g_KH);
    cudaGetSymbolAddress((void**)&VH,  g_VH);
    cudaGetSymbolAddress((void**)&KR,  g_KR);
    cudaGetSymbolAddress((void**)&QT,  g_QT);
    cudaGetSymbolAddress((void**)&QW,  g_QW);
    cudaGetSymbolAddress((void**)&QR,  g_QR);
    cudaGetSymbolAddress((void**)&QG,  g_QG);
    cudaGetSymbolAddress((void**)&AC,  g_AC);
    cudaGetSymbolAddress((void**)&BD,  g_BD);
    cudaGetSymbolAddress((void**)&AV,  g_AV);
    cudaGetSymbolAddress((void**)&AV2, g_AV2);
    cudaGetSymbolAddress((void**)&ATTH, g_ATTH);
    cudaGetSymbolAddress((void**)&ATTG, g_ATTG);
    cudaGetSymbolAddress((void**)&FF1, g_FF1);
    cudaGetSymbolAddress((void**)&FF2, g_FF2);

    const int T = 256;
    const int MH = QLEN * BSZ;     // 4096
    const int MG = NPRED * BSZ;    // 1024

    // attn_pv smem size
    const int APV_SMEM = (3 * (128 * 20) * 2 + 3 * (16 * 72) + 2 * (128 * 20) + 512) * 4;
    cudaFuncSetAttribute(attn_pv, cudaFuncAttributeMaxDynamicSharedMemorySize, APV_SMEM);

    // ---- shared projections ----
    launchG<128,1,1,1>(Xh, kw, KH, MH, DM, DM, DM, 0, DM, 0, DM, 0, nullptr, 0, 1, 0, 1);
    launchG<128,1,1,1>(Xh, vw, VH, MH, DM, DM, DM, 0, DM, 0, DM, 0, nullptr, 0, 1, 0, 1);
    launchG<128,1,1,1>(R,  rw, KR, RLEN * BSZ, DM, DM, DM, 0, DM, 0, DM, 0, nullptr, 0, 1, 0, 1);

    // ================= h-stream =================
    launchG<128,1,1,1>(Xh, qw, QW, MH, DM, DM, DM, 0, DM, 0, DM, 0, rwb, 0, 1, 0, 1, QR, rrb);

    launchG<128,0,0,0>(QW, KH, AC, QLEN, KLEN, DH, 4096, 64, 4096, 64,
                   KLEN, (long)QLEN * KLEN, nullptr, 0, NB);
    launchG<128,0,0,0,1>(QR, KR, BD, QLEN, RLEN, DH, 4096, 64, 4096, 64,
                   1024, (long)QLEN * 1024, nullptr, 0, NB, 1, 0, nullptr, nullptr, mh);
    attn_pv<<<dim3(QLEN / 128, NB), T, APV_SMEM>>>(AC, BD, VH, AV);
    ln_res<<<MH, T>>>(AV, Xh, lns, lnb, ATTH);

    // ================= g-stream =================
    launchG<128,1,1,1>(Xg, qw, QG, MG, DM, DM, DM, 0, DM, 0, DM, 0, nullptr, 0, 1);
    bgemm_tc<<<dim3(DM / BN, QLEN / BM, BSZ), T>>>(TM, QG, QT, QLEN, DM, NPRED,
              4, 4096, 1,   4096, 1, DM,   4096, DM);
    add_bias2<<<4096, T>>>(QT, rwb, rrb, QW, QR, (long)MH * DM);

    launchG<128,0,0,0>(QW, KH, AC, QLEN, KLEN, DH, 4096, 64, 4096, 64,
                   KLEN, (long)QLEN * KLEN, nullptr, 0, NB);
    launchG<128,0,0,0,1>(QR, KR, BD, QLEN, RLEN, DH, 4096, 64, 4096, 64,
                   1024, (long)QLEN * 1024, nullptr, 0, NB, 1, 0, nullptr, nullptr, mg);
    attn_pv<<<dim3(QLEN / 128, NB), T, APV_SMEM>>>(AC, BD, VH, AV);
    bgemm_tc<<<dim3(DM / BN, NPRED / BM, BSZ), T>>>(TM, AV, AV2, NPRED, DM, QLEN,
              4096, 4, 1,   4096, 1, DM,   4096, DM);
    ln_res<<<MG, T>>>(AV2, Xg, lns, lnb, ATTG);

    // ================= FFN (h) =================
    launchG<128,1,1,1>(ATTH, w1, FF1, MH, DI, DM, DM, 0, DI, 0, DI, 0, b1, 1, 1, 0, 1);
    launchG<128,1,0,1>(FF1, w2, FF2, MH, DM, DI, DI, 0, DM, 0, DM, 0, b2, 0, 1);
    ln_res<<<MH, T>>>(FF2, ATTH, fls, flb, out);

    // ================= FFN (g) =================
    launchG<128,1,1,1>(ATTG, w1, FF1, MG, DI, DM, DM, 0, DI, 0, DI, 0, b1, 1, 1, 0, 1);
    launchG<128,1,0,1>(FF1, w2, FF2, MG, DM, DI, DI, 0, DM, 0, DM, 0, b2, 0, 1);
    ln_res<<<MG, T>>>(FF2, ATTG, fls, flb, out + (long)MH * DM);
}

// round 12
// speedup vs baseline: 1.0590x; 1.0590x over previous
#include <cuda_runtime.h>
#include <cstdint>
#include <math.h>

#define QLEN  1024
#define KLEN  1024
#define RLEN  2048
#define NPRED 256
#define BSZ   4
#define NH    16
#define DH    64
#define DM    1024
#define DI    4096
#define NB    (BSZ*NH)   /* 64 head-batches */

typedef unsigned int u32;

// ---------------------------------------------------------------------------
// Scratch (device globals; allocation in kernel_launch is forbidden)
// ---------------------------------------------------------------------------
__device__ float g_KH [QLEN*BSZ*DM];
__device__ float g_VH [QLEN*BSZ*DM];
__device__ float g_KR [RLEN*BSZ*DM];
__device__ float g_QT [QLEN*BSZ*DM];
__device__ float g_QW [QLEN*BSZ*DM];
__device__ float g_QR [QLEN*BSZ*DM];
__device__ float g_QG [NPRED*BSZ*DM];
__device__ float g_AC [(long)NB*QLEN*KLEN];
__device__ float g_BD [(long)NB*QLEN*KLEN];   // compact shifted scores (masked)
__device__ float g_AV [QLEN*BSZ*DM];
__device__ float g_AV2[NPRED*BSZ*DM];
__device__ float g_ATTH[QLEN*BSZ*DM];
__device__ float g_ATTG[NPRED*BSZ*DM];
__device__ float g_FF1[QLEN*BSZ*DI];
__device__ float g_FF2[QLEN*BSZ*DM];

// ---------------------------------------------------------------------------
__device__ __forceinline__ u32 f2tf32(float v)
{
    u32 r;
    asm("cvt.rna.tf32.f32 %0, %1;" : "=r"(r) : "f"(v));
    return r;
}
__device__ __forceinline__ u32 cvtu(u32 raw)
{
    u32 r;
    asm("cvt.rna.tf32.f32 %0, %1;" : "=r"(r) : "f"(__uint_as_float(raw)));
    return r;
}
__device__ __forceinline__ float tf32r(float v)
{
    return __uint_as_float(f2tf32(v));
}

__device__ __forceinline__ void mma_tf32(float* c, const u32* a, const u32* b)
{
    asm volatile(
        "mma.sync.aligned.m16n8k8.row.col.f32.tf32.tf32.f32 "
        "{%0,%1,%2,%3}, {%4,%5,%6,%7}, {%8,%9}, {%0,%1,%2,%3};\n"
        : "+f"(c[0]), "+f"(c[1]), "+f"(c[2]), "+f"(c[3])
        : "r"(a[0]), "r"(a[1]), "r"(a[2]), "r"(a[3]), "r"(b[0]), "r"(b[1]));
}

__device__ __forceinline__ void ldsm4(u32& r0, u32& r1, u32& r2, u32& r3, u32 addr)
{
    asm volatile(
        "ldmatrix.sync.aligned.m8n8.x4.shared.b16 {%0,%1,%2,%3}, [%4];\n"
        : "=r"(r0), "=r"(r1), "=r"(r2), "=r"(r3) : "r"(addr));
}

__device__ __forceinline__ void cpa16(u32 saddr, const void* gaddr)
{
    asm volatile("cp.async.cg.shared.global [%0], [%1], 16;\n"
                 :: "r"(saddr), "l"(gaddr));
}
__device__ __forceinline__ void cpa_commit() { asm volatile("cp.async.commit_group;\n"); }
__device__ __forceinline__ void cpa_wait1()  { asm volatile("cp.async.wait_group 1;\n"); }

// ===========================================================================
// FAST GEMM. A k-contiguous, M%128==0, K%16==0, N%TBN==0.
//   BTR=1: B n-contiguous. BTR=0: B k-contiguous.
//   CVA/CVB: tf32-convert at fragment load.
//   SHIFT=1: BD epilogue — scatter row-shifted (j=col+row-1024) into a
//            1024-wide buffer with the attention mask folded in.
// 3-stage cp.async pipeline, 128 x TBN tile, 256 threads.
// ===========================================================================
#define SK 20   /* A / B(ldsm) smem row stride in u32 */

template<int TBN, int BTR, int CVA, int CVB, int SHIFT>
__global__ __launch_bounds__(256, 2) void gemm_fast(
    const float* __restrict__ A, const float* __restrict__ B,
    float* __restrict__ C, int K,
    long ldaI, long bsA,
    long ldb,  long bsB,
    long ldcI, long bsC,
    const float* __restrict__ bias, int act, int diagskip, int rndC,
    float* __restrict__ C2, const float* __restrict__ bias2,
    const float* __restrict__ smask)
{
    constexpr int WARPS_M = (TBN == 128) ? 2 : 4;
    constexpr int MT      = (128 / WARPS_M) / 16;     // 4 / 2
    constexpr int NT      = 4;
    constexpr int NCHB    = TBN / 64;
    constexpr int BSTR    = BTR ? (TBN + 8) : SK;
    constexpr int ABUF    = 128 * SK * 4;
    constexpr int BBUF    = (BTR ? 16 * BSTR : TBN * SK) * 4;

    extern __shared__ __align__(16) u32 dyn[];
    u32* Asp = dyn;
    u32* Bsp = dyn + 3 * 128 * SK;

    const int i0 = blockIdx.y * 128;
    const int j0 = blockIdx.x * TBN;
    if (diagskip && (i0 + j0 < 770 || i0 + j0 > 2047)) return;

    const int z = blockIdx.z;
    const float* Ab = A + (long)z * bsA;
    const float* Bb = B + (long)z * bsB;
    float*       Cb = C + (long)z * bsC;

    const int tid  = threadIdx.x;
    const int warp = tid >> 5;
    const int lane = tid & 31;
    const int g = lane >> 2;
    const int t = lane & 3;
    const int wm = (warp % WARPS_M) * (128 / WARPS_M);
    const int wn = (warp / WARPS_M) * 32;

    const u32 sa_base = (u32)__cvta_generic_to_shared(Asp);
    const u32 sb_base = (u32)__cvta_generic_to_shared(Bsp);

    const int mi = lane >> 3;
    const int ri = lane & 7;
    u32 aoff[MT];
#pragma unroll
    for (int mt = 0; mt < MT; mt++)
        aoff[mt] = ((u32)(wm + mt * 16 + (mi & 1) * 8 + ri) * SK + (u32)(mi >> 1) * 4) * 4;
    u32 boff[2];
#pragma unroll
    for (int p = 0; p < 2; p++)
        boff[p] = ((u32)(wn + p * 16 + (mi >> 1) * 8 + ri) * SK + (u32)(mi & 1) * 4) * 4;

    const int arow = tid >> 2;
    const int aq4  = (tid & 3) * 4;
    u32 sAo[2];
    const float* gA[2];
    sAo[0] = ((u32)arow * SK + aq4) * 4;
    sAo[1] = ((u32)(arow + 64) * SK + aq4) * 4;
    gA[0] = Ab + (long)(i0 + arow) * ldaI + aq4;
    gA[1] = Ab + (long)(i0 + arow + 64) * ldaI + aq4;

    u32 sBo[NCHB];
    const float* gB[NCHB];
    long bstep;
    if (BTR) {
        bstep = 16 * ldb;
#pragma unroll
        for (int u = 0; u < NCHB; u++) {
            int idx = tid + 256 * u;
            int k  = idx / (TBN / 4);
            int n4 = (idx % (TBN / 4)) * 4;
            sBo[u] = ((u32)k * BSTR + n4) * 4;
            gB[u]  = Bb + (long)k * ldb + (j0 + n4);
        }
    } else {
        bstep = 16;
#pragma unroll
        for (int u = 0; u < NCHB; u++) {
            int idx = tid + 256 * u;
            int n  = idx >> 2;
            int q4 = (idx & 3) * 4;
            sBo[u] = ((u32)n * SK + q4) * 4;
            gB[u]  = Bb + (long)(j0 + n) * ldb + q4;
        }
    }

    const int nk = K >> 4;

    auto issue = [&](int stage, int it) {
        u32 ab = sa_base + (u32)stage * ABUF;
        u32 bb = sb_base + (u32)stage * BBUF;
        long ka = (long)it * 16;
        long kb = (long)it * bstep;
        cpa16(ab + sAo[0], gA[0] + ka);
        cpa16(ab + sAo[1], gA[1] + ka);
#pragma unroll
        for (int u = 0; u < NCHB; u++)
            cpa16(bb + sBo[u], gB[u] + kb);
    };

    float acc[MT][NT][4];
#pragma unroll
    for (int mt = 0; mt < MT; mt++)
#pragma unroll
        for (int nt = 0; nt < NT; nt++)
#pragma unroll
            for (int e = 0; e < 4; e++) acc[mt][nt][e] = 0.0f;

    issue(0, 0); cpa_commit();
    if (nk > 1) issue(1, 1);
    cpa_commit();

    int buf = 0;
    for (int it = 0; it < nk; it++) {
        cpa_wait1();
        __syncthreads();

        const u32 ab = sa_base + (u32)buf * ABUF;
        const u32 bb = sb_base + (u32)buf * BBUF;
        const u32* Brow = Bsp + buf * (BBUF / 4);

#pragma unroll
        for (int kk = 0; kk < 2; kk++) {
            const u32 ksb = kk * 32;
            const int ks  = kk * 8;
            u32 af[MT][4], bf2[2][4];
#pragma unroll
            for (int mt = 0; mt < MT; mt++) {
                ldsm4(af[mt][0], af[mt][1], af[mt][2], af[mt][3], ab + aoff[mt] + ksb);
                if (CVA) {
                    af[mt][0] = cvtu(af[mt][0]); af[mt][1] = cvtu(af[mt][1]);
                    af[mt][2] = cvtu(af[mt][2]); af[mt][3] = cvtu(af[mt][3]);
                }
            }
            if (BTR) {
#pragma unroll
                for (int p = 0; p < 2; p++) {
                    int c = wn + p * 16;
                    bf2[p][0] = Brow[(ks + t) * BSTR + c + g];
                    bf2[p][1] = Brow[(ks + t + 4) * BSTR + c + g];
                    bf2[p][2] = Brow[(ks + t) * BSTR + c + 8 + g];
                    bf2[p][3] = Brow[(ks + t + 4) * BSTR + c + 8 + g];
                    if (CVB) {
                        bf2[p][0] = cvtu(bf2[p][0]); bf2[p][1] = cvtu(bf2[p][1]);
                        bf2[p][2] = cvtu(bf2[p][2]); bf2[p][3] = cvtu(bf2[p][3]);
                    }
                }
            } else {
#pragma unroll
                for (int p = 0; p < 2; p++) {
                    ldsm4(bf2[p][0], bf2[p][1], bf2[p][2], bf2[p][3], bb + boff[p] + ksb);
                    if (CVB) {
                        bf2[p][0] = cvtu(bf2[p][0]); bf2[p][1] = cvtu(bf2[p][1]);
                        bf2[p][2] = cvtu(bf2[p][2]); bf2[p][3] = cvtu(bf2[p][3]);
                    }
                }
            }
#pragma unroll
            for (int mt = 0; mt < MT; mt++)
#pragma unroll
                for (int nt = 0; nt < NT; nt++)
                    mma_tf32(acc[mt][nt], af[mt], &bf2[nt >> 1][(nt & 1) * 2]);
        }

        int ns = it + 2;
        if (ns < nk) issue(ns >= 3 ? ns - 3 * (ns / 3) : ns, ns);
        cpa_commit();
        buf = (buf == 2) ? 0 : buf + 1;
    }

    if (SHIFT) {
        // scatter: BDs[i][j] = acc - 8e30*mask[i][j][b],  j = col + i - 1024
        const int b = z >> 4;
#pragma unroll
        for (int mt = 0; mt < MT; mt++)
#pragma unroll
            for (int nt = 0; nt < NT; nt++) {
                int col = j0 + wn + nt * 8 + t * 2;
#pragma unroll
                for (int half = 0; half < 2; half++) {
                    int row = i0 + wm + mt * 16 + g + half * 8;
#pragma unroll
                    for (int e2 = 0; e2 < 2; e2++) {
                        int j = col + e2 + row - 1024;
                        if (j >= 0 && j < 1024) {
                            float v = acc[mt][nt][half * 2 + e2]
                                    - 8e30f * smask[((long)row * 1024 + j) * 4 + b];
                            Cb[(long)row * ldcI + j] = v;
                        }
                    }
                }
            }
        return;
    }

    // normal epilogue
#pragma unroll
    for (int mt = 0; mt < MT; mt++) {
#pragma unroll
        for (int nt = 0; nt < NT; nt++) {
            int col = j0 + wn + nt * 8 + t * 2;
            float b0 = 0.0f, b1 = 0.0f;
            if (bias) { b0 = bias[col]; b1 = bias[col + 1]; }
            float c0 = 0.0f, c1 = 0.0f;
            if (C2) { c0 = bias2[col]; c1 = bias2[col + 1]; }
#pragma unroll
            for (int half = 0; half < 2; half++) {
                int row = i0 + wm + mt * 16 + g + half * 8;
                float a0 = acc[mt][nt][half * 2 + 0];
                float a1 = acc[mt][nt][half * 2 + 1];
                float v0 = a0 + b0, v1 = a1 + b1;
                if (act) {
                    v0 = 0.5f * v0 * (1.0f + erff(v0 * 0.70710678118654752f));
                    v1 = 0.5f * v1 * (1.0f + erff(v1 * 0.70710678118654752f));
                }
                if (rndC) { v0 = tf32r(v0); v1 = tf32r(v1); }
                *(float2*)&Cb[(long)row * ldcI + col] = make_float2(v0, v1);
                if (C2) {
                    float w0 = a0 + c0, w1 = a1 + c1;
                    if (rndC) { w0 = tf32r(w0); w1 = tf32r(w1); }
                    *(float2*)&C2[(long)row * ldcI + col] = make_float2(w0, w1);
                }
            }
        }
    }
}

// ===========================================================================
// Generic fallback — used only for the two target-mapping GEMMs.
// ===========================================================================
#define BM 128
#define BN 64
#define BKT 16

__global__ __launch_bounds__(256) void bgemm_tc(
    const float* __restrict__ A, const float* __restrict__ B,
    float* __restrict__ C,
    int M, int N, int K,
    long ldaI, long ldaK, long bsA,
    long ldbK, long ldbJ, long bsB,
    long ldcI, long bsC)
{
    __shared__ u32 As[2][BM][BKT + 1];
    __shared__ u32 Bs[2][BN][BKT + 1];

    const int z = blockIdx.z;
    const float* Ab = A + (long)z * bsA;
    const float* Bb = B + (long)z * bsB;
    float*       Cb = C + (long)z * bsC;

    const int i0 = blockIdx.y * BM;
    const int j0 = blockIdx.x * BN;
    const int tid  = threadIdx.x;
    const int warp = tid >> 5;
    const int lane = tid & 31;
    const int g = lane >> 2;
    const int t = lane & 3;
    const int wm = (warp & 3) * 32;
    const int wn = (warp >> 2) * 32;

    const bool ak1 = (ldaK == 1);
    const bool bj1 = (ldbJ == 1);

    float acc[2][4][4];
#pragma unroll
    for (int mt = 0; mt < 2; mt++)
#pragma unroll
        for (int nt = 0; nt < 4; nt++)
#pragma unroll
            for (int e = 0; e < 4; e++) acc[mt][nt][e] = 0.0f;

    float ra[8], rb[4];

    auto stage = [&](int k0) {
#pragma unroll
        for (int u = 0; u < 8; u++) {
            int e = tid + u * 256;
            int i, k;
            if (ak1) { k = e & 15; i = e >> 4; }
            else     { i = e & 127; k = e >> 7; }
            int gi = i0 + i, gk = k0 + k;
            ra[u] = (gi < M && gk < K) ? Ab[(long)gi * ldaI + (long)gk * ldaK] : 0.0f;
        }
#pragma unroll
        for (int u = 0; u < 4; u++) {
            int e = tid + u * 256;
            int n, k;
            if (bj1) { n = e & 63; k = e >> 6; }
            else     { k = e & 15; n = e >> 4; }
            int gn = j0 + n, gk = k0 + k;
            rb[u] = (gn < N && gk < K) ? Bb[(long)gk * ldbK + (long)gn * ldbJ] : 0.0f;
        }
    };
    auto commit = [&](int buf) {
#pragma unroll
        for (int u = 0; u < 8; u++) {
            int e = tid + u * 256;
            int i, k;
            if (ak1) { k = e & 15; i = e >> 4; }
            else     { i = e & 127; k = e >> 7; }
            As[buf][i][k] = f2tf32(ra[u]);
        }
#pragma unroll
        for (int u = 0; u < 4; u++) {
            int e = tid + u * 256;
            int n, k;
            if (bj1) { n = e & 63; k = e >> 6; }
            else     { k = e & 15; n = e >> 4; }
            Bs[buf][n][k] = f2tf32(rb[u]);
        }
    };

    stage(0);
    commit(0);
    __syncthreads();

    int buf = 0;
    for (int k0 = 0; k0 < K; k0 += BKT) {
        const bool more = (k0 + BKT) < K;
        if (more) stage(k0 + BKT);

#pragma unroll
        for (int kk = 0; kk < 2; kk++) {
            const int ks = kk * 8;
            u32 af[2][4], bf[4][2];
#pragma unroll
            for (int mt = 0; mt < 2; mt++) {
                int r = wm + mt * 16;
                af[mt][0] = As[buf][r + g    ][ks + t];
                af[mt][1] = As[buf][r + g + 8][ks + t];
                af[mt][2] = As[buf][r + g    ][ks + t + 4];
                af[mt][3] = As[buf][r + g + 8][ks + t + 4];
            }
#pragma unroll
            for (int nt = 0; nt < 4; nt++) {
                int c = wn + nt * 8;
                bf[nt][0] = Bs[buf][c + g][ks + t];
                bf[nt][1] = Bs[buf][c + g][ks + t + 4];
            }
#pragma unroll
            for (int mt = 0; mt < 2; mt++)
#pragma unroll
                for (int nt = 0; nt < 4; nt++)
                    mma_tf32(acc[mt][nt], af[mt], bf[nt]);
        }

        if (more) {
            commit(buf ^ 1);
            __syncthreads();
            buf ^= 1;
        }
    }

#pragma unroll
    for (int mt = 0; mt < 2; mt++) {
#pragma unroll
        for (int nt = 0; nt < 4; nt++) {
            int col = j0 + wn + nt * 8 + t * 2;
            if (col >= N) continue;
#pragma unroll
            for (int half = 0; half < 2; half++) {
                int row = i0 + wm + mt * 16 + g + half * 8;
                if (row >= M) continue;
                *(float2*)&Cb[(long)row * ldcI + col] =
                    make_float2(acc[mt][nt][half * 2 + 0], acc[mt][nt][half * 2 + 1]);
            }
        }
    }
}

// ---------------------------------------------------------------------------
__global__ void add_bias2(const float* __restrict__ src,
                          const float* __restrict__ bw,
                          const float* __restrict__ br,
                          float* __restrict__ dw, float* __restrict__ dr, long n)
{
    long idx = (long)blockIdx.x * blockDim.x + threadIdx.x;
    long stride = (long)gridDim.x * blockDim.x;
    for (; idx < n; idx += stride) {
        int c = (int)(idx & (DM - 1));
        float v = src[idx];
        dw[idx] = tf32r(v + bw[c]);
        dr[idx] = tf32r(v + br[c]);
    }
}

// ---------------------------------------------------------------------------
// Softmax over compact pre-shifted scores (mask already folded into BDS):
//   P[z,i,j] = softmax_j( (AC[z,i,j] + BDS[z,i,j]) * 0.125 ), tf32-rounded.
// Sequential reads only. One block per (i, z); 256 threads, 4 elems each.
// ---------------------------------------------------------------------------
__global__ void softmax_c(const float* __restrict__ AC,
                          const float* __restrict__ BDS,
                          float* __restrict__ P)
{
    const int i = blockIdx.x;
    const int z = blockIdx.y;
    const float* ac = AC  + ((long)z * QLEN + i) * KLEN;
    const float* bd = BDS + ((long)z * QLEN + i) * KLEN;
    float*       p  = P   + ((long)z * QLEN + i) * KLEN;

    __shared__ float red[256];
    const int tid = threadIdx.x;

    float vals[4];
    float lm = -1e38f;
#pragma unroll
    for (int r = 0; r < 4; r++) {
        int j = tid + r * 256;
        float s = (ac[j] + bd[j]) * 0.125f;
        vals[r] = s;
        lm = fmaxf(lm, s);
    }
    red[tid] = lm; __syncthreads();
    for (int s = 128; s > 0; s >>= 1) {
        if (tid < s) red[tid] = fmaxf(red[tid], red[tid + s]);
        __syncthreads();
    }
    float mx = red[0]; __syncthreads();

    float ls = 0.0f;
#pragma unroll
    for (int r = 0; r < 4; r++) {
        vals[r] = __expf(vals[r] - mx);
        ls += vals[r];
    }
    red[tid] = ls; __syncthreads();
    for (int s = 128; s > 0; s >>= 1) {
        if (tid < s) red[tid] += red[tid + s];
        __syncthreads();
    }
    float inv = 1.0f / red[0];
#pragma unroll
    for (int r = 0; r < 4; r++)
        p[tid + r * 256] = tf32r(vals[r] * inv);
}

// ---------------------------------------------------------------------------
__global__ void ln_res(const float* __restrict__ x, const float* __restrict__ res,
                       const float* __restrict__ sc, const float* __restrict__ bi,
                       float* __restrict__ out)
{
    const long row = blockIdx.x;
    const float* xr = x   + row * DM;
    const float* rr = res + row * DM;
    float*       o  = out + row * DM;
    const int tid = threadIdx.x;

    __shared__ float red[256];

    float v[4];
    float s = 0.0f;
#pragma unroll
    for (int r = 0; r < 4; r++) {
        int c = tid + r * 256;
        v[r] = xr[c] + rr[c];
        s += v[r];
    }
    red[tid] = s; __syncthreads();
    for (int st = 128; st > 0; st >>= 1) {
        if (tid < st) red[tid] += red[tid + st];
        __syncthreads();
    }
    float mean = red[0] * (1.0f / DM); __syncthreads();

    float sq = 0.0f;
#pragma unroll
    for (int r = 0; r < 4; r++) {
        float d = v[r] - mean;
        sq += d * d;
    }
    red[tid] = sq; __syncthreads();
    for (int st = 128; st > 0; st >>= 1) {
        if (tid < st) red[tid] += red[tid + st];
        __syncthreads();
    }
    float rstd = rsqrtf(red[0] * (1.0f / DM) + 1e-8f);
#pragma unroll
    for (int r = 0; r < 4; r++) {
        int c = tid + r * 256;
        o[c] = (v[r] - mean) * rstd * sc[c] + bi[c];
    }
}

// ---------------------------------------------------------------------------
template<int TBN, int BTR, int CVA, int CVB, int SHIFT = 0>
static void launchG(const float* A, const float* B, float* C,
                    int M, int N, int K,
                    long ldaI, long bsA, long ldb, long bsB,
                    long ldcI, long bsC,
                    const float* bias, int act, int nb,
                    int diagskip = 0, int rndC = 0,
                    float* C2 = nullptr, const float* bias2 = nullptr,
                    const float* smask = nullptr)
{
    constexpr int BSTR = BTR ? (TBN + 8) : SK;
    constexpr int SMEM = (3 * 128 * SK + 3 * (BTR ? 16 * BSTR : TBN * SK)) * 4;
    cudaFuncSetAttribute(gemm_fast<TBN, BTR, CVA, CVB, SHIFT>,
                         cudaFuncAttributeMaxDynamicSharedMemorySize, SMEM);
    gemm_fast<TBN, BTR, CVA, CVB, SHIFT><<<dim3(N / TBN, M / 128, nb), 256, SMEM>>>(
        A, B, C, K, ldaI, bsA, ldb, bsB, ldcI, bsC, bias, act, diagskip, rndC,
        C2, bias2, smask);
}

extern "C" void kernel_launch(void* const* d_in, const int* in_sizes, int n_in,
                              void* d_out, int out_size)
{
    const float* Xh  = (const float*)d_in[0];
    const float* Xg  = (const float*)d_in[1];
    const float* mh  = (const float*)d_in[2];
    const float* mg  = (const float*)d_in[3];
    const float* R   = (const float*)d_in[4];
    const float* TM  = (const float*)d_in[5];
    const float* qw  = (const float*)d_in[6];
    const float* kw  = (const float*)d_in[7];
    const float* vw  = (const float*)d_in[8];
    const float* rw  = (const float*)d_in[9];
    const float* rrb = (const float*)d_in[10];
    const float* rwb = (const float*)d_in[11];
    const float* lns = (const float*)d_in[12];
    const float* lnb = (const float*)d_in[13];
    const float* w1  = (const float*)d_in[14];
    const float* b1  = (const float*)d_in[15];
    const float* w2  = (const float*)d_in[16];
    const float* b2  = (const float*)d_in[17];
    const float* fls = (const float*)d_in[18];
    const float* flb = (const float*)d_in[19];
    float* out = (float*)d_out;

    float *KH, *VH, *KR, *QT, *QW, *QR, *QG, *AC, *BD, *AV, *AV2,
          *ATTH, *ATTG, *FF1, *FF2;
    cudaGetSymbolAddress((void**)&KH,  g_KH);
    cudaGetSymbolAddress((void**)&VH,  g_VH);
    cudaGetSymbolAddress((void**)&KR,  g_KR);
    cudaGetSymbolAddress((void**)&QT,  g_QT);
    cudaGetSymbolAddress((void**)&QW,  g_QW);
    cudaGetSymbolAddress((void**)&QR,  g_QR);
    cudaGetSymbolAddress((void**)&QG,  g_QG);
    cudaGetSymbolAddress((void**)&AC,  g_AC);
    cudaGetSymbolAddress((void**)&BD,  g_BD);
    cudaGetSymbolAddress((void**)&AV,  g_AV);
    cudaGetSymbolAddress((void**)&AV2, g_AV2);
    cudaGetSymbolAddress((void**)&ATTH, g_ATTH);
    cudaGetSymbolAddress((void**)&ATTG, g_ATTG);
    cudaGetSymbolAddress((void**)&FF1, g_FF1);
    cudaGetSymbolAddress((void**)&FF2, g_FF2);

    const int T = 256;
    const int MH = QLEN * BSZ;     // 4096
    const int MG = NPRED * BSZ;    // 1024

    // ---- shared projections ----
    launchG<128,1,1,1>(Xh, kw, KH, MH, DM, DM, DM, 0, DM, 0, DM, 0, nullptr, 0, 1, 0, 1);
    launchG<128,1,1,1>(Xh, vw, VH, MH, DM, DM, DM, 0, DM, 0, DM, 0, nullptr, 0, 1, 0, 1);
    launchG<128,1,1,1>(R,  rw, KR, RLEN * BSZ, DM, DM, DM, 0, DM, 0, DM, 0, nullptr, 0, 1, 0, 1);

    // ================= h-stream =================
    launchG<128,1,1,1>(Xh, qw, QW, MH, DM, DM, DM, 0, DM, 0, DM, 0, rwb, 0, 1, 0, 1, QR, rrb);

    launchG<128,0,0,0>(QW, KH, AC, QLEN, KLEN, DH, 4096, 64, 4096, 64,
                   KLEN, (long)QLEN * KLEN, nullptr, 0, NB);
    launchG<128,0,0,0,1>(QR, KR, BD, QLEN, RLEN, DH, 4096, 64, 4096, 64,
                   1024, (long)QLEN * 1024, nullptr, 0, NB, 1, 0, nullptr, nullptr, mh);
    softmax_c<<<dim3(QLEN, NB), T>>>(AC, BD, AC);
    launchG<64,1,0,0>(AC, VH, AV, QLEN, DH, KLEN, KLEN, (long)QLEN * KLEN,
                  4096, 64, 4096, 64, nullptr, 0, NB);
    ln_res<<<MH, T>>>(AV, Xh, lns, lnb, ATTH);

    // ================= g-stream =================
    launchG<128,1,1,1>(Xg, qw, QG, MG, DM, DM, DM, 0, DM, 0, DM, 0, nullptr, 0, 1);
    bgemm_tc<<<dim3(DM / BN, QLEN / BM, BSZ), T>>>(TM, QG, QT, QLEN, DM, NPRED,
              4, 4096, 1,   4096, 1, DM,   4096, DM);
    add_bias2<<<4096, T>>>(QT, rwb, rrb, QW, QR, (long)MH * DM);

    launchG<128,0,0,0>(QW, KH, AC, QLEN, KLEN, DH, 4096, 64, 4096, 64,
                   KLEN, (long)QLEN * KLEN, nullptr, 0, NB);
    launchG<128,0,0,0,1>(QR, KR, BD, QLEN, RLEN, DH, 4096, 64, 4096, 64,
                   1024, (long)QLEN * 1024, nullptr, 0, NB, 1, 0, nullptr, nullptr, mg);
    softmax_c<<<dim3(QLEN, NB), T>>>(AC, BD, AC);
    launchG<64,1,0,0>(AC, VH, AV, QLEN, DH, KLEN, KLEN, (long)QLEN * KLEN,
                  4096, 64, 4096, 64, nullptr, 0, NB);
    bgemm_tc<<<dim3(DM / BN, NPRED / BM, BSZ), T>>>(TM, AV, AV2, NPRED, DM, QLEN,
              4096, 4, 1,   4096, 1, DM,   4096, DM);
    ln_res<<<MG, T>>>(AV2, Xg, lns, lnb, ATTG);

    // ================= FFN (h) =================
    launchG<128,1,1,1>(ATTH, w1, FF1, MH, DI, DM, DM, 0, DI, 0, DI, 0, b1, 1, 1, 0, 1);
    launchG<128,1,0,1>(FF1, w2, FF2, MH, DM, DI, DI, 0, DM, 0, DM, 0, b2, 0, 1);
    ln_res<<<MH, T>>>(FF2, ATTH, fls, flb, out);

    // ================= FFN (g) =================
    launchG<128,1,1,1>(ATTG, w1, FF1, MG, DI, DM, DM, 0, DI, 0, DI, 0, b1, 1, 1, 0, 1);
    launchG<128,1,0,1>(FF1, w2, FF2, MG, DM, DI, DI, 0, DM, 0, DM, 0, b2, 0, 1);
    ln_res<<<MG, T>>>(FF2, ATTG, fls, flb, out + (long)MH * DM);
}

// round 13
// speedup vs baseline: 1.1554x; 1.0910x over previous
#include <cuda_runtime.h>
#include <cstdint>
#include <math.h>

#define QLEN  1024
#define KLEN  1024
#define RLEN  2048
#define NPRED 256
#define BSZ   4
#define NH    16
#define DH    64
#define DM    1024
#define DI    4096
#define NB    (BSZ*NH)   /* 64 head-batches */

typedef unsigned int u32;

// ---------------------------------------------------------------------------
// Scratch (device globals; allocation in kernel_launch is forbidden)
// ---------------------------------------------------------------------------
__device__ float g_KH [QLEN*BSZ*DM];
__device__ float g_VH [QLEN*BSZ*DM];
__device__ float g_KR [RLEN*BSZ*DM];
__device__ float g_QT [QLEN*BSZ*DM];
__device__ float g_QW [QLEN*BSZ*DM];
__device__ float g_QR [QLEN*BSZ*DM];
__device__ float g_QG [NPRED*BSZ*DM];
__device__ float g_AC [(long)NB*QLEN*KLEN];
__device__ float g_BD [(long)NB*QLEN*RLEN];
__device__ float g_MT [(long)BSZ*QLEN*KLEN];   // transposed mask [b][i][j]
__device__ float g_AV [QLEN*BSZ*DM];
__device__ float g_AV2[NPRED*BSZ*DM];
__device__ float g_ATTH[QLEN*BSZ*DM];
__device__ float g_ATTG[NPRED*BSZ*DM];
__device__ float g_FF1[QLEN*BSZ*DI];
__device__ float g_FF2[QLEN*BSZ*DM];

// ---------------------------------------------------------------------------
__device__ __forceinline__ u32 f2tf32(float v)
{
    u32 r;
    asm("cvt.rna.tf32.f32 %0, %1;" : "=r"(r) : "f"(v));
    return r;
}
__device__ __forceinline__ u32 cvtu(u32 raw)
{
    u32 r;
    asm("cvt.rna.tf32.f32 %0, %1;" : "=r"(r) : "f"(__uint_as_float(raw)));
    return r;
}
__device__ __forceinline__ float tf32r(float v)
{
    return __uint_as_float(f2tf32(v));
}

__device__ __forceinline__ void mma_tf32(float* c, const u32* a, const u32* b)
{
    asm volatile(
        "mma.sync.aligned.m16n8k8.row.col.f32.tf32.tf32.f32 "
        "{%0,%1,%2,%3}, {%4,%5,%6,%7}, {%8,%9}, {%0,%1,%2,%3};\n"
        : "+f"(c[0]), "+f"(c[1]), "+f"(c[2]), "+f"(c[3])
        : "r"(a[0]), "r"(a[1]), "r"(a[2]), "r"(a[3]), "r"(b[0]), "r"(b[1]));
}

__device__ __forceinline__ void ldsm4(u32& r0, u32& r1, u32& r2, u32& r3, u32 addr)
{
    asm volatile(
        "ldmatrix.sync.aligned.m8n8.x4.shared.b16 {%0,%1,%2,%3}, [%4];\n"
        : "=r"(r0), "=r"(r1), "=r"(r2), "=r"(r3) : "r"(addr));
}

__device__ __forceinline__ void cpa16(u32 saddr, const void* gaddr)
{
    asm volatile("cp.async.cg.shared.global [%0], [%1], 16;\n"
                 :: "r"(saddr), "l"(gaddr));
}
__device__ __forceinline__ void cpa_commit() { asm volatile("cp.async.commit_group;\n"); }
__device__ __forceinline__ void cpa_wait1()  { asm volatile("cp.async.wait_group 1;\n"); }

// ===========================================================================
// FAST GEMM. A k-contiguous, M%128==0, K%16==0, N%TBN==0.
//   BTR=1: B n-contiguous. BTR=0: B k-contiguous.
//   CVA/CVB: tf32-convert at fragment load (0 when producer stored
//   tf32-rounded values — bit-identical results).
// 3-stage cp.async pipeline, 128 x TBN tile, 256 threads.
// ===========================================================================
#define SK 20   /* A / B(ldsm) smem row stride in u32 */

template<int TBN, int BTR, int CVA, int CVB>
__global__ __launch_bounds__(256, 2) void gemm_fast(
    const float* __restrict__ A, const float* __restrict__ B,
    float* __restrict__ C, int K,
    long ldaI, long bsA,
    long ldb,  long bsB,
    long ldcI, long bsC,
    const float* __restrict__ bias, int act, int diagskip, int rndC,
    float* __restrict__ C2, const float* __restrict__ bias2)
{
    constexpr int WARPS_M = (TBN == 128) ? 2 : 4;
    constexpr int MT      = (128 / WARPS_M) / 16;     // 4 / 2
    constexpr int NT      = 4;
    constexpr int NCHB    = TBN / 64;
    constexpr int BSTR    = BTR ? (TBN + 8) : SK;
    constexpr int ABUF    = 128 * SK * 4;
    constexpr int BBUF    = (BTR ? 16 * BSTR : TBN * SK) * 4;

    extern __shared__ __align__(16) u32 dyn[];
    u32* Asp = dyn;
    u32* Bsp = dyn + 3 * 128 * SK;

    const int i0 = blockIdx.y * 128;
    const int j0 = blockIdx.x * TBN;
    if (diagskip && (i0 + j0 < 770 || i0 + j0 > 2047)) return;

    const int z = blockIdx.z;
    const float* Ab = A + (long)z * bsA;
    const float* Bb = B + (long)z * bsB;
    float*       Cb = C + (long)z * bsC;

    const int tid  = threadIdx.x;
    const int warp = tid >> 5;
    const int lane = tid & 31;
    const int g = lane >> 2;
    const int t = lane & 3;
    const int wm = (warp % WARPS_M) * (128 / WARPS_M);
    const int wn = (warp / WARPS_M) * 32;

    const u32 sa_base = (u32)__cvta_generic_to_shared(Asp);
    const u32 sb_base = (u32)__cvta_generic_to_shared(Bsp);

    const int mi = lane >> 3;
    const int ri = lane & 7;
    u32 aoff[MT];
#pragma unroll
    for (int mt = 0; mt < MT; mt++)
        aoff[mt] = ((u32)(wm + mt * 16 + (mi & 1) * 8 + ri) * SK + (u32)(mi >> 1) * 4) * 4;
    u32 boff[2];
#pragma unroll
    for (int p = 0; p < 2; p++)
        boff[p] = ((u32)(wn + p * 16 + (mi >> 1) * 8 + ri) * SK + (u32)(mi & 1) * 4) * 4;

    const int arow = tid >> 2;
    const int aq4  = (tid & 3) * 4;
    u32 sAo[2];
    const float* gA[2];
    sAo[0] = ((u32)arow * SK + aq4) * 4;
    sAo[1] = ((u32)(arow + 64) * SK + aq4) * 4;
    gA[0] = Ab + (long)(i0 + arow) * ldaI + aq4;
    gA[1] = Ab + (long)(i0 + arow + 64) * ldaI + aq4;

    u32 sBo[NCHB];
    const float* gB[NCHB];
    long bstep;
    if (BTR) {
        bstep = 16 * ldb;
#pragma unroll
        for (int u = 0; u < NCHB; u++) {
            int idx = tid + 256 * u;
            int k  = idx / (TBN / 4);
            int n4 = (idx % (TBN / 4)) * 4;
            sBo[u] = ((u32)k * BSTR + n4) * 4;
            gB[u]  = Bb + (long)k * ldb + (j0 + n4);
        }
    } else {
        bstep = 16;
#pragma unroll
        for (int u = 0; u < NCHB; u++) {
            int idx = tid + 256 * u;
            int n  = idx >> 2;
            int q4 = (idx & 3) * 4;
            sBo[u] = ((u32)n * SK + q4) * 4;
            gB[u]  = Bb + (long)(j0 + n) * ldb + q4;
        }
    }

    const int nk = K >> 4;

    auto issue = [&](int stage, int it) {
        u32 ab = sa_base + (u32)stage * ABUF;
        u32 bb = sb_base + (u32)stage * BBUF;
        long ka = (long)it * 16;
        long kb = (long)it * bstep;
        cpa16(ab + sAo[0], gA[0] + ka);
        cpa16(ab + sAo[1], gA[1] + ka);
#pragma unroll
        for (int u = 0; u < NCHB; u++)
            cpa16(bb + sBo[u], gB[u] + kb);
    };

    float acc[MT][NT][4];
#pragma unroll
    for (int mt = 0; mt < MT; mt++)
#pragma unroll
        for (int nt = 0; nt < NT; nt++)
#pragma unroll
            for (int e = 0; e < 4; e++) acc[mt][nt][e] = 0.0f;

    issue(0, 0); cpa_commit();
    if (nk > 1) issue(1, 1);
    cpa_commit();

    int buf = 0;
    for (int it = 0; it < nk; it++) {
        cpa_wait1();
        __syncthreads();

        const u32 ab = sa_base + (u32)buf * ABUF;
        const u32 bb = sb_base + (u32)buf * BBUF;
        const u32* Brow = Bsp + buf * (BBUF / 4);

#pragma unroll
        for (int kk = 0; kk < 2; kk++) {
            const u32 ksb = kk * 32;
            const int ks  = kk * 8;
            u32 af[MT][4], bf2[2][4];
#pragma unroll
            for (int mt = 0; mt < MT; mt++) {
                ldsm4(af[mt][0], af[mt][1], af[mt][2], af[mt][3], ab + aoff[mt] + ksb);
                if (CVA) {
                    af[mt][0] = cvtu(af[mt][0]); af[mt][1] = cvtu(af[mt][1]);
                    af[mt][2] = cvtu(af[mt][2]); af[mt][3] = cvtu(af[mt][3]);
                }
            }
            if (BTR) {
#pragma unroll
                for (int p = 0; p < 2; p++) {
                    int c = wn + p * 16;
                    bf2[p][0] = Brow[(ks + t) * BSTR + c + g];
                    bf2[p][1] = Brow[(ks + t + 4) * BSTR + c + g];
                    bf2[p][2] = Brow[(ks + t) * BSTR + c + 8 + g];
                    bf2[p][3] = Brow[(ks + t + 4) * BSTR + c + 8 + g];
                    if (CVB) {
                        bf2[p][0] = cvtu(bf2[p][0]); bf2[p][1] = cvtu(bf2[p][1]);
                        bf2[p][2] = cvtu(bf2[p][2]); bf2[p][3] = cvtu(bf2[p][3]);
                    }
                }
            } else {
#pragma unroll
                for (int p = 0; p < 2; p++) {
                    ldsm4(bf2[p][0], bf2[p][1], bf2[p][2], bf2[p][3], bb + boff[p] + ksb);
                    if (CVB) {
                        bf2[p][0] = cvtu(bf2[p][0]); bf2[p][1] = cvtu(bf2[p][1]);
                        bf2[p][2] = cvtu(bf2[p][2]); bf2[p][3] = cvtu(bf2[p][3]);
                    }
                }
            }
#pragma unroll
            for (int mt = 0; mt < MT; mt++)
#pragma unroll
                for (int nt = 0; nt < NT; nt++)
                    mma_tf32(acc[mt][nt], af[mt], &bf2[nt >> 1][(nt & 1) * 2]);
        }

        int ns = it + 2;
        if (ns < nk) issue(ns >= 3 ? ns - 3 * (ns / 3) : ns, ns);
        cpa_commit();
        buf = (buf == 2) ? 0 : buf + 1;
    }

    // epilogue
#pragma unroll
    for (int mt = 0; mt < MT; mt++) {
#pragma unroll
        for (int nt = 0; nt < NT; nt++) {
            int col = j0 + wn + nt * 8 + t * 2;
            float b0 = 0.0f, b1 = 0.0f;
            if (bias) { b0 = bias[col]; b1 = bias[col + 1]; }
            float c0 = 0.0f, c1 = 0.0f;
            if (C2) { c0 = bias2[col]; c1 = bias2[col + 1]; }
#pragma unroll
            for (int half = 0; half < 2; half++) {
                int row = i0 + wm + mt * 16 + g + half * 8;
                float a0 = acc[mt][nt][half * 2 + 0];
                float a1 = acc[mt][nt][half * 2 + 1];
                float v0 = a0 + b0, v1 = a1 + b1;
                if (act) {
                    v0 = 0.5f * v0 * (1.0f + erff(v0 * 0.70710678118654752f));
                    v1 = 0.5f * v1 * (1.0f + erff(v1 * 0.70710678118654752f));
                }
                if (rndC) { v0 = tf32r(v0); v1 = tf32r(v1); }
                *(float2*)&Cb[(long)row * ldcI + col] = make_float2(v0, v1);
                if (C2) {
                    float w0 = a0 + c0, w1 = a1 + c1;
                    if (rndC) { w0 = tf32r(w0); w1 = tf32r(w1); }
                    *(float2*)&C2[(long)row * ldcI + col] = make_float2(w0, w1);
                }
            }
        }
    }
}

// ===========================================================================
// Generic fallback — used only for the two target-mapping GEMMs.
// ===========================================================================
#define BM 128
#define BN 64
#define BKT 16

__global__ __launch_bounds__(256) void bgemm_tc(
    const float* __restrict__ A, const float* __restrict__ B,
    float* __restrict__ C,
    int M, int N, int K,
    long ldaI, long ldaK, long bsA,
    long ldbK, long ldbJ, long bsB,
    long ldcI, long bsC)
{
    __shared__ u32 As[2][BM][BKT + 1];
    __shared__ u32 Bs[2][BN][BKT + 1];

    const int z = blockIdx.z;
    const float* Ab = A + (long)z * bsA;
    const float* Bb = B + (long)z * bsB;
    float*       Cb = C + (long)z * bsC;

    const int i0 = blockIdx.y * BM;
    const int j0 = blockIdx.x * BN;
    const int tid  = threadIdx.x;
    const int warp = tid >> 5;
    const int lane = tid & 31;
    const int g = lane >> 2;
    const int t = lane & 3;
    const int wm = (warp & 3) * 32;
    const int wn = (warp >> 2) * 32;

    const bool ak1 = (ldaK == 1);
    const bool bj1 = (ldbJ == 1);

    float acc[2][4][4];
#pragma unroll
    for (int mt = 0; mt < 2; mt++)
#pragma unroll
        for (int nt = 0; nt < 4; nt++)
#pragma unroll
            for (int e = 0; e < 4; e++) acc[mt][nt][e] = 0.0f;

    float ra[8], rb[4];

    auto stage = [&](int k0) {
#pragma unroll
        for (int u = 0; u < 8; u++) {
            int e = tid + u * 256;
            int i, k;
            if (ak1) { k = e & 15; i = e >> 4; }
            else     { i = e & 127; k = e >> 7; }
            int gi = i0 + i, gk = k0 + k;
            ra[u] = (gi < M && gk < K) ? Ab[(long)gi * ldaI + (long)gk * ldaK] : 0.0f;
        }
#pragma unroll
        for (int u = 0; u < 4; u++) {
            int e = tid + u * 256;
            int n, k;
            if (bj1) { n = e & 63; k = e >> 6; }
            else     { k = e & 15; n = e >> 4; }
            int gn = j0 + n, gk = k0 + k;
            rb[u] = (gn < N && gk < K) ? Bb[(long)gk * ldbK + (long)gn * ldbJ] : 0.0f;
        }
    };
    auto commit = [&](int buf) {
#pragma unroll
        for (int u = 0; u < 8; u++) {
            int e = tid + u * 256;
            int i, k;
            if (ak1) { k = e & 15; i = e >> 4; }
            else     { i = e & 127; k = e >> 7; }
            As[buf][i][k] = f2tf32(ra[u]);
        }
#pragma unroll
        for (int u = 0; u < 4; u++) {
            int e = tid + u * 256;
            int n, k;
            if (bj1) { n = e & 63; k = e >> 6; }
            else     { k = e & 15; n = e >> 4; }
            Bs[buf][n][k] = f2tf32(rb[u]);
        }
    };

    stage(0);
    commit(0);
    __syncthreads();

    int buf = 0;
    for (int k0 = 0; k0 < K; k0 += BKT) {
        const bool more = (k0 + BKT) < K;
        if (more) stage(k0 + BKT);

#pragma unroll
        for (int kk = 0; kk < 2; kk++) {
            const int ks = kk * 8;
            u32 af[2][4], bf[4][2];
#pragma unroll
            for (int mt = 0; mt < 2; mt++) {
                int r = wm + mt * 16;
                af[mt][0] = As[buf][r + g    ][ks + t];
                af[mt][1] = As[buf][r + g + 8][ks + t];
                af[mt][2] = As[buf][r + g    ][ks + t + 4];
                af[mt][3] = As[buf][r + g + 8][ks + t + 4];
            }
#pragma unroll
            for (int nt = 0; nt < 4; nt++) {
                int c = wn + nt * 8;
                bf[nt][0] = Bs[buf][c + g][ks + t];
                bf[nt][1] = Bs[buf][c + g][ks + t + 4];
            }
#pragma unroll
            for (int mt = 0; mt < 2; mt++)
#pragma unroll
                for (int nt = 0; nt < 4; nt++)
                    mma_tf32(acc[mt][nt], af[mt], bf[nt]);
        }

        if (more) {
            commit(buf ^ 1);
            __syncthreads();
            buf ^= 1;
        }
    }

#pragma unroll
    for (int mt = 0; mt < 2; mt++) {
#pragma unroll
        for (int nt = 0; nt < 4; nt++) {
            int col = j0 + wn + nt * 8 + t * 2;
            if (col >= N) continue;
#pragma unroll
            for (int half = 0; half < 2; half++) {
                int row = i0 + wm + mt * 16 + g + half * 8;
                if (row >= M) continue;
                *(float2*)&Cb[(long)row * ldcI + col] =
                    make_float2(acc[mt][nt][half * 2 + 0], acc[mt][nt][half * 2 + 1]);
            }
        }
    }
}

// ---------------------------------------------------------------------------
__global__ void add_bias2(const float* __restrict__ src,
                          const float* __restrict__ bw,
                          const float* __restrict__ br,
                          float* __restrict__ dw, float* __restrict__ dr, long n)
{
    long idx = (long)blockIdx.x * blockDim.x + threadIdx.x;
    long stride = (long)gridDim.x * blockDim.x;
    for (; idx < n; idx += stride) {
        int c = (int)(idx & (DM - 1));
        float v = src[idx];
        dw[idx] = tf32r(v + bw[c]);
        dr[idx] = tf32r(v + br[c]);
    }
}

// ---------------------------------------------------------------------------
// Mask transpose: MT[b][i][j] = mask[i][j][b].
// Strided reads happen ONCE here (instead of per-head in softmax).
// ---------------------------------------------------------------------------
__global__ void mask_t(const float* __restrict__ m, float* __restrict__ mt)
{
    const int i = blockIdx.x;
    const int b = blockIdx.y;
    const float* src = m + (long)i * KLEN * BSZ + b;
    float* dst = mt + ((long)b * QLEN + i) * KLEN;
    for (int j = threadIdx.x; j < KLEN; j += blockDim.x)
        dst[j] = src[(long)j * BSZ];
}

// ---------------------------------------------------------------------------
// Softmax with relative shift gather; mask read from transposed MT (coalesced,
// shared across the 16 heads of each batch). Stores tf32-rounded P in place.
// ---------------------------------------------------------------------------
__global__ void softmax_shift(const float* __restrict__ AC,
                              const float* __restrict__ BD,
                              const float* __restrict__ MTm,
                              float* __restrict__ P)
{
    const int i = blockIdx.x;
    const int z = blockIdx.y;
    const int b = z >> 4;
    const float* ac = AC + ((long)z * QLEN + i) * KLEN;
    const float* bd = BD + ((long)z * QLEN + i) * RLEN;
    const float* mk = MTm + ((long)b * QLEN + i) * KLEN;
    float*       p  = P  + ((long)z * QLEN + i) * KLEN;

    __shared__ float red[256];
    const int tid = threadIdx.x;

    float vals[4];
    float lm = -1e38f;
#pragma unroll
    for (int r = 0; r < 4; r++) {
        int j = tid + r * 256;
        float s = (ac[j] + bd[j - i + KLEN]) * 0.125f - 1e30f * mk[j];
        vals[r] = s;
        lm = fmaxf(lm, s);
    }
    red[tid] = lm; __syncthreads();
    for (int s = 128; s > 0; s >>= 1) {
        if (tid < s) red[tid] = fmaxf(red[tid], red[tid + s]);
        __syncthreads();
    }
    float mx = red[0]; __syncthreads();

    float ls = 0.0f;
#pragma unroll
    for (int r = 0; r < 4; r++) {
        vals[r] = __expf(vals[r] - mx);
        ls += vals[r];
    }
    red[tid] = ls; __syncthreads();
    for (int s = 128; s > 0; s >>= 1) {
        if (tid < s) red[tid] += red[tid + s];
        __syncthreads();
    }
    float inv = 1.0f / red[0];
#pragma unroll
    for (int r = 0; r < 4; r++)
        p[tid + r * 256] = tf32r(vals[r] * inv);
}

// ---------------------------------------------------------------------------
__global__ void ln_res(const float* __restrict__ x, const float* __restrict__ res,
                       const float* __restrict__ sc, const float* __restrict__ bi,
                       float* __restrict__ out)
{
    const long row = blockIdx.x;
    const float* xr = x   + row * DM;
    const float* rr = res + row * DM;
    float*       o  = out + row * DM;
    const int tid = threadIdx.x;

    __shared__ float red[256];

    float v[4];
    float s = 0.0f;
#pragma unroll
    for (int r = 0; r < 4; r++) {
        int c = tid + r * 256;
        v[r] = xr[c] + rr[c];
        s += v[r];
    }
    red[tid] = s; __syncthreads();
    for (int st = 128; st > 0; st >>= 1) {
        if (tid < st) red[tid] += red[tid + st];
        __syncthreads();
    }
    float mean = red[0] * (1.0f / DM); __syncthreads();

    float sq = 0.0f;
#pragma unroll
    for (int r = 0; r < 4; r++) {
        float d = v[r] - mean;
        sq += d * d;
    }
    red[tid] = sq; __syncthreads();
    for (int st = 128; st > 0; st >>= 1) {
        if (tid < st) red[tid] += red[tid + st];
        __syncthreads();
    }
    float rstd = rsqrtf(red[0] * (1.0f / DM) + 1e-8f);
#pragma unroll
    for (int r = 0; r < 4; r++) {
        int c = tid + r * 256;
        o[c] = (v[r] - mean) * rstd * sc[c] + bi[c];
    }
}

// ---------------------------------------------------------------------------
template<int TBN, int BTR, int CVA, int CVB>
static void launchG(const float* A, const float* B, float* C,
                    int M, int N, int K,
                    long ldaI, long bsA, long ldb, long bsB,
                    long ldcI, long bsC,
                    const float* bias, int act, int nb,
                    int diagskip = 0, int rndC = 0,
                    float* C2 = nullptr, const float* bias2 = nullptr)
{
    constexpr int BSTR = BTR ? (TBN + 8) : SK;
    constexpr int SMEM = (3 * 128 * SK + 3 * (BTR ? 16 * BSTR : TBN * SK)) * 4;
    cudaFuncSetAttribute(gemm_fast<TBN, BTR, CVA, CVB>,
                         cudaFuncAttributeMaxDynamicSharedMemorySize, SMEM);
    gemm_fast<TBN, BTR, CVA, CVB><<<dim3(N / TBN, M / 128, nb), 256, SMEM>>>(
        A, B, C, K, ldaI, bsA, ldb, bsB, ldcI, bsC, bias, act, diagskip, rndC, C2, bias2);
}

extern "C" void kernel_launch(void* const* d_in, const int* in_sizes, int n_in,
                              void* d_out, int out_size)
{
    const float* Xh  = (const float*)d_in[0];
    const float* Xg  = (const float*)d_in[1];
    const float* mh  = (const float*)d_in[2];
    const float* mg  = (const float*)d_in[3];
    const float* R   = (const float*)d_in[4];
    const float* TM  = (const float*)d_in[5];
    const float* qw  = (const float*)d_in[6];
    const float* kw  = (const float*)d_in[7];
    const float* vw  = (const float*)d_in[8];
    const float* rw  = (const float*)d_in[9];
    const float* rrb = (const float*)d_in[10];
    const float* rwb = (const float*)d_in[11];
    const float* lns = (const float*)d_in[12];
    const float* lnb = (const float*)d_in[13];
    const float* w1  = (const float*)d_in[14];
    const float* b1  = (const float*)d_in[15];
    const float* w2  = (const float*)d_in[16];
    const float* b2  = (const float*)d_in[17];
    const float* fls = (const float*)d_in[18];
    const float* flb = (const float*)d_in[19];
    float* out = (float*)d_out;

    float *KH, *VH, *KR, *QT, *QW, *QR, *QG, *AC, *BD, *MTp, *AV, *AV2,
          *ATTH, *ATTG, *FF1, *FF2;
    cudaGetSymbolAddress((void**)&KH,  g_KH);
    cudaGetSymbolAddress((void**)&VH,  g_VH);
    cudaGetSymbolAddress((void**)&KR,  g_KR);
    cudaGetSymbolAddress((void**)&QT,  g_QT);
    cudaGetSymbolAddress((void**)&QW,  g_QW);
    cudaGetSymbolAddress((void**)&QR,  g_QR);
    cudaGetSymbolAddress((void**)&QG,  g_QG);
    cudaGetSymbolAddress((void**)&AC,  g_AC);
    cudaGetSymbolAddress((void**)&BD,  g_BD);
    cudaGetSymbolAddress((void**)&MTp, g_MT);
    cudaGetSymbolAddress((void**)&AV,  g_AV);
    cudaGetSymbolAddress((void**)&AV2, g_AV2);
    cudaGetSymbolAddress((void**)&ATTH, g_ATTH);
    cudaGetSymbolAddress((void**)&ATTG, g_ATTG);
    cudaGetSymbolAddress((void**)&FF1, g_FF1);
    cudaGetSymbolAddress((void**)&FF2, g_FF2);

    const int T = 256;
    const int MH = QLEN * BSZ;     // 4096
    const int MG = NPRED * BSZ;    // 1024

    // ---- shared projections ----
    launchG<128,1,1,1>(Xh, kw, KH, MH, DM, DM, DM, 0, DM, 0, DM, 0, nullptr, 0, 1, 0, 1);
    launchG<128,1,1,1>(Xh, vw, VH, MH, DM, DM, DM, 0, DM, 0, DM, 0, nullptr, 0, 1, 0, 1);
    launchG<128,1,1,1>(R,  rw, KR, RLEN * BSZ, DM, DM, DM, 0, DM, 0, DM, 0, nullptr, 0, 1, 0, 1);

    // ================= h-stream =================
    launchG<128,1,1,1>(Xh, qw, QW, MH, DM, DM, DM, 0, DM, 0, DM, 0, rwb, 0, 1, 0, 1, QR, rrb);

    launchG<128,0,0,0>(QW, KH, AC, QLEN, KLEN, DH, 4096, 64, 4096, 64,
                   KLEN, (long)QLEN * KLEN, nullptr, 0, NB);
    launchG<128,0,0,0>(QR, KR, BD, QLEN, RLEN, DH, 4096, 64, 4096, 64,
                   RLEN, (long)QLEN * RLEN, nullptr, 0, NB, 1);
    mask_t<<<dim3(QLEN, BSZ), T>>>(mh, MTp);
    softmax_shift<<<dim3(QLEN, NB), T>>>(AC, BD, MTp, AC);
    launchG<64,1,0,0>(AC, VH, AV, QLEN, DH, KLEN, KLEN, (long)QLEN * KLEN,
                  4096, 64, 4096, 64, nullptr, 0, NB);
    ln_res<<<MH, T>>>(AV, Xh, lns, lnb, ATTH);

    // ================= g-stream =================
    launchG<128,1,1,1>(Xg, qw, QG, MG, DM, DM, DM, 0, DM, 0, DM, 0, nullptr, 0, 1);
    bgemm_tc<<<dim3(DM / BN, QLEN / BM, BSZ), T>>>(TM, QG, QT, QLEN, DM, NPRED,
              4, 4096, 1,   4096, 1, DM,   4096, DM);
    add_bias2<<<4096, T>>>(QT, rwb, rrb, QW, QR, (long)MH * DM);

    launchG<128,0,0,0>(QW, KH, AC, QLEN, KLEN, DH, 4096, 64, 4096, 64,
                   KLEN, (long)QLEN * KLEN, nullptr, 0, NB);
    launchG<128,0,0,0>(QR, KR, BD, QLEN, RLEN, DH, 4096, 64, 4096, 64,
                   RLEN, (long)QLEN * RLEN, nullptr, 0, NB, 1);
    mask_t<<<dim3(QLEN, BSZ), T>>>(mg, MTp);
    softmax_shift<<<dim3(QLEN, NB), T>>>(AC, BD, MTp, AC);
    launchG<64,1,0,0>(AC, VH, AV, QLEN, DH, KLEN, KLEN, (long)QLEN * KLEN,
                  4096, 64, 4096, 64, nullptr, 0, NB);
    bgemm_tc<<<dim3(DM / BN, NPRED / BM, BSZ), T>>>(TM, AV, AV2, NPRED, DM, QLEN,
              4096, 4, 1,   4096, 1, DM,   4096, DM);
    ln_res<<<MG, T>>>(AV2, Xg, lns, lnb, ATTG);

    // ================= FFN (h) =================
    launchG<128,1,1,1>(ATTH, w1, FF1, MH, DI, DM, DM, 0, DI, 0, DI, 0, b1, 1, 1, 0, 1);
    launchG<128,1,0,1>(FF1, w2, FF2, MH, DM, DI, DI, 0, DM, 0, DM, 0, b2, 0, 1);
    ln_res<<<MH, T>>>(FF2, ATTH, fls, flb, out);

    // ================= FFN (g) =================
    launchG<128,1,1,1>(ATTG, w1, FF1, MG, DI, DM, DM, 0, DI, 0, DI, 0, b1, 1, 1, 0, 1);
    launchG<128,1,0,1>(FF1, w2, FF2, MG, DM, DI, DI, 0, DM, 0, DM, 0, b2, 0, 1);
    ln_res<<<MG, T>>>(FF2, ATTG, fls, flb, out + (long)MH * DM);
}

// round 14
// speedup vs baseline: 1.2269x; 1.0619x over previous
#include <cuda_runtime.h>
#include <cstdint>
#include <math.h>

#define QLEN  1024
#define KLEN  1024
#define RLEN  2048
#define NPRED 256
#define BSZ   4
#define NH    16
#define DH    64
#define DM    1024
#define DI    4096
#define NB    (BSZ*NH)   /* 64 head-batches */

typedef unsigned int u32;

// ---------------------------------------------------------------------------
// Scratch (device globals; allocation in kernel_launch is forbidden)
// ---------------------------------------------------------------------------
__device__ float g_KH [QLEN*BSZ*DM];
__device__ float g_VH [QLEN*BSZ*DM];
__device__ float g_KR [RLEN*BSZ*DM];
__device__ float g_QT [QLEN*BSZ*DM];    // XhT (early) / target-mapping temp (late)
__device__ float g_QW [QLEN*BSZ*DM];
__device__ float g_QR [QLEN*BSZ*DM];
__device__ float g_QG [NPRED*BSZ*DM];
__device__ float g_AC [(long)NB*QLEN*KLEN];
__device__ float g_BD [(long)NB*QLEN*RLEN];
__device__ float g_MT [(long)BSZ*QLEN*KLEN];   // transposed mask [b][i][j]
__device__ float g_AV [QLEN*BSZ*DM];
__device__ float g_AV2[NPRED*BSZ*DM];
__device__ float g_ATTH[QLEN*BSZ*DM];
__device__ float g_ATTG[NPRED*BSZ*DM];
__device__ float g_FF1[QLEN*BSZ*DI];
__device__ float g_FF2[QLEN*BSZ*DM];

// ---------------------------------------------------------------------------
__device__ __forceinline__ u32 f2tf32(float v)
{
    u32 r;
    asm("cvt.rna.tf32.f32 %0, %1;" : "=r"(r) : "f"(v));
    return r;
}
__device__ __forceinline__ u32 cvtu(u32 raw)
{
    u32 r;
    asm("cvt.rna.tf32.f32 %0, %1;" : "=r"(r) : "f"(__uint_as_float(raw)));
    return r;
}
__device__ __forceinline__ float tf32r(float v)
{
    return __uint_as_float(f2tf32(v));
}

__device__ __forceinline__ void mma_tf32(float* c, const u32* a, const u32* b)
{
    asm volatile(
        "mma.sync.aligned.m16n8k8.row.col.f32.tf32.tf32.f32 "
        "{%0,%1,%2,%3}, {%4,%5,%6,%7}, {%8,%9}, {%0,%1,%2,%3};\n"
        : "+f"(c[0]), "+f"(c[1]), "+f"(c[2]), "+f"(c[3])
        : "r"(a[0]), "r"(a[1]), "r"(a[2]), "r"(a[3]), "r"(b[0]), "r"(b[1]));
}

__device__ __forceinline__ void ldsm4(u32& r0, u32& r1, u32& r2, u32& r3, u32 addr)
{
    asm volatile(
        "ldmatrix.sync.aligned.m8n8.x4.shared.b16 {%0,%1,%2,%3}, [%4];\n"
        : "=r"(r0), "=r"(r1), "=r"(r2), "=r"(r3) : "r"(addr));
}

__device__ __forceinline__ void cpa16(u32 saddr, const void* gaddr)
{
    asm volatile("cp.async.cg.shared.global [%0], [%1], 16;\n"
                 :: "r"(saddr), "l"(gaddr));
}
__device__ __forceinline__ void cpa_commit() { asm volatile("cp.async.commit_group;\n"); }
__device__ __forceinline__ void cpa_wait1()  { asm volatile("cp.async.wait_group 1;\n"); }

// ===========================================================================
// FAST GEMM, BK=32. A k-contiguous, M%128==0, K%32==0, N%TBN==0.
//   BTR=1: B n-contiguous. BTR=0: B k-contiguous.
//   CVA/CVB: tf32-convert at fragment load (0 when producer stored
//   tf32-rounded values — bit-identical results).
// 3-stage cp.async pipeline, 128 x TBN tile, 256 threads.
// ===========================================================================
#define SK2 36   /* A / B(ldsm) smem row stride in u32 (32 + 4 pad) */

template<int TBN, int BTR, int CVA, int CVB>
__global__ __launch_bounds__(256, 2) void gemm_fast(
    const float* __restrict__ A, const float* __restrict__ B,
    float* __restrict__ C, int K,
    long ldaI, long bsA,
    long ldb,  long bsB,
    long ldcI, long bsC,
    const float* __restrict__ bias, int act, int diagskip, int rndC,
    float* __restrict__ C2, const float* __restrict__ bias2)
{
    constexpr int WARPS_M = (TBN == 128) ? 2 : 4;
    constexpr int MT      = (128 / WARPS_M) / 16;     // 4 / 2
    constexpr int NT      = 4;
    constexpr int NCHB    = TBN / 32;                 // B cp.async per thread
    constexpr int BSTR    = BTR ? (TBN + 8) : SK2;
    constexpr int ABUF    = 128 * SK2 * 4;            // 18432 B per stage
    constexpr int BBUF    = (BTR ? 32 * BSTR : TBN * SK2) * 4;

    extern __shared__ __align__(16) u32 dyn[];
    u32* Asp = dyn;
    u32* Bsp = dyn + 3 * 128 * SK2;

    const int i0 = blockIdx.y * 128;
    const int j0 = blockIdx.x * TBN;
    if (diagskip && (i0 + j0 < 770 || i0 + j0 > 2047)) return;

    const int z = blockIdx.z;
    const float* Ab = A + (long)z * bsA;
    const float* Bb = B + (long)z * bsB;
    float*       Cb = C + (long)z * bsC;

    const int tid  = threadIdx.x;
    const int warp = tid >> 5;
    const int lane = tid & 31;
    const int g = lane >> 2;
    const int t = lane & 3;
    const int wm = (warp % WARPS_M) * (128 / WARPS_M);
    const int wn = (warp / WARPS_M) * 32;

    const u32 sa_base = (u32)__cvta_generic_to_shared(Asp);
    const u32 sb_base = (u32)__cvta_generic_to_shared(Bsp);

    const int mi = lane >> 3;
    const int ri = lane & 7;
    u32 aoff[MT];
#pragma unroll
    for (int mt = 0; mt < MT; mt++)
        aoff[mt] = ((u32)(wm + mt * 16 + (mi & 1) * 8 + ri) * SK2 + (u32)(mi >> 1) * 4) * 4;
    u32 boff[2];
#pragma unroll
    for (int p = 0; p < 2; p++)
        boff[p] = ((u32)(wn + p * 16 + (mi >> 1) * 8 + ri) * SK2 + (u32)(mi & 1) * 4) * 4;

    // ---- A staging: 128 rows x 32 floats, 4 cpa16 per thread ----
    u32 sAo[4];
    const float* gA[4];
#pragma unroll
    for (int u = 0; u < 4; u++) {
        int idx = tid + 256 * u;
        int row = idx >> 3, q4 = (idx & 7) * 4;
        sAo[u] = ((u32)row * SK2 + q4) * 4;
        gA[u]  = Ab + (long)(i0 + row) * ldaI + q4;
    }

    // ---- B staging ----
    u32 sBo[NCHB];
    const float* gB[NCHB];
    long bstep;
    if (BTR) {
        bstep = 32 * ldb;
#pragma unroll
        for (int u = 0; u < NCHB; u++) {
            int idx = tid + 256 * u;
            int k  = idx / (TBN / 4);
            int n4 = (idx % (TBN / 4)) * 4;
            sBo[u] = ((u32)k * BSTR + n4) * 4;
            gB[u]  = Bb + (long)k * ldb + (j0 + n4);
        }
    } else {
        bstep = 32;
#pragma unroll
        for (int u = 0; u < NCHB; u++) {
            int idx = tid + 256 * u;
            int row = idx >> 3, q4 = (idx & 7) * 4;
            sBo[u] = ((u32)row * SK2 + q4) * 4;
            gB[u]  = Bb + (long)(j0 + row) * ldb + q4;
        }
    }

    const int nk = K >> 5;   // BK = 32

    auto issue = [&](int stage, int it) {
        u32 ab = sa_base + (u32)stage * ABUF;
        u32 bb = sb_base + (u32)stage * BBUF;
        long ka = (long)it * 32;
        long kb = (long)it * bstep;
#pragma unroll
        for (int u = 0; u < 4; u++)
            cpa16(ab + sAo[u], gA[u] + ka);
#pragma unroll
        for (int u = 0; u < NCHB; u++)
            cpa16(bb + sBo[u], gB[u] + kb);
    };

    float acc[MT][NT][4];
#pragma unroll
    for (int mt = 0; mt < MT; mt++)
#pragma unroll
        for (int nt = 0; nt < NT; nt++)
#pragma unroll
            for (int e = 0; e < 4; e++) acc[mt][nt][e] = 0.0f;

    issue(0, 0); cpa_commit();
    if (nk > 1) issue(1, 1);
    cpa_commit();

    int buf = 0;
    for (int it = 0; it < nk; it++) {
        cpa_wait1();
        __syncthreads();

        const u32 ab = sa_base + (u32)buf * ABUF;
        const u32 bb = sb_base + (u32)buf * BBUF;
        const u32* Brow = Bsp + buf * (BBUF / 4);

#pragma unroll
        for (int kk = 0; kk < 4; kk++) {
            const u32 ksb = kk * 32;   // 8 k * 4 B
            const int ks  = kk * 8;
            u32 af[MT][4], bf2[2][4];
#pragma unroll
            for (int mt = 0; mt < MT; mt++) {
                ldsm4(af[mt][0], af[mt][1], af[mt][2], af[mt][3], ab + aoff[mt] + ksb);
                if (CVA) {
                    af[mt][0] = cvtu(af[mt][0]); af[mt][1] = cvtu(af[mt][1]);
                    af[mt][2] = cvtu(af[mt][2]); af[mt][3] = cvtu(af[mt][3]);
                }
            }
            if (BTR) {
#pragma unroll
                for (int p = 0; p < 2; p++) {
                    int c = wn + p * 16;
                    bf2[p][0] = Brow[(ks + t) * BSTR + c + g];
                    bf2[p][1] = Brow[(ks + t + 4) * BSTR + c + g];
                    bf2[p][2] = Brow[(ks + t) * BSTR + c + 8 + g];
                    bf2[p][3] = Brow[(ks + t + 4) * BSTR + c + 8 + g];
                    if (CVB) {
                        bf2[p][0] = cvtu(bf2[p][0]); bf2[p][1] = cvtu(bf2[p][1]);
                        bf2[p][2] = cvtu(bf2[p][2]); bf2[p][3] = cvtu(bf2[p][3]);
                    }
                }
            } else {
#pragma unroll
                for (int p = 0; p < 2; p++) {
                    ldsm4(bf2[p][0], bf2[p][1], bf2[p][2], bf2[p][3], bb + boff[p] + ksb);
                    if (CVB) {
                        bf2[p][0] = cvtu(bf2[p][0]); bf2[p][1] = cvtu(bf2[p][1]);
                        bf2[p][2] = cvtu(bf2[p][2]); bf2[p][3] = cvtu(bf2[p][3]);
                    }
                }
            }
#pragma unroll
            for (int mt = 0; mt < MT; mt++)
#pragma unroll
                for (int nt = 0; nt < NT; nt++)
                    mma_tf32(acc[mt][nt], af[mt], &bf2[nt >> 1][(nt & 1) * 2]);
        }

        int ns = it + 2;
        if (ns < nk) issue(ns % 3, ns);
        cpa_commit();
        buf = (buf == 2) ? 0 : buf + 1;
    }

    // epilogue
#pragma unroll
    for (int mt = 0; mt < MT; mt++) {
#pragma unroll
        for (int nt = 0; nt < NT; nt++) {
            int col = j0 + wn + nt * 8 + t * 2;
            float b0 = 0.0f, b1 = 0.0f;
            if (bias) { b0 = bias[col]; b1 = bias[col + 1]; }
            float c0 = 0.0f, c1 = 0.0f;
            if (C2) { c0 = bias2[col]; c1 = bias2[col + 1]; }
#pragma unroll
            for (int half = 0; half < 2; half++) {
                int row = i0 + wm + mt * 16 + g + half * 8;
                float a0 = acc[mt][nt][half * 2 + 0];
                float a1 = acc[mt][nt][half * 2 + 1];
                float v0 = a0 + b0, v1 = a1 + b1;
                if (act) {
                    v0 = 0.5f * v0 * (1.0f + erff(v0 * 0.70710678118654752f));
                    v1 = 0.5f * v1 * (1.0f + erff(v1 * 0.70710678118654752f));
                }
                if (rndC) { v0 = tf32r(v0); v1 = tf32r(v1); }
                *(float2*)&Cb[(long)row * ldcI + col] = make_float2(v0, v1);
                if (C2) {
                    float w0 = a0 + c0, w1 = a1 + c1;
                    if (rndC) { w0 = tf32r(w0); w1 = tf32r(w1); }
                    *(float2*)&C2[(long)row * ldcI + col] = make_float2(w0, w1);
                }
            }
        }
    }
}

// ===========================================================================
// Generic fallback — used only for the two target-mapping GEMMs.
// ===========================================================================
#define BM 128
#define BN 64
#define BKT 16

__global__ __launch_bounds__(256) void bgemm_tc(
    const float* __restrict__ A, const float* __restrict__ B,
    float* __restrict__ C,
    int M, int N, int K,
    long ldaI, long ldaK, long bsA,
    long ldbK, long ldbJ, long bsB,
    long ldcI, long bsC)
{
    __shared__ u32 As[2][BM][BKT + 1];
    __shared__ u32 Bs[2][BN][BKT + 1];

    const int z = blockIdx.z;
    const float* Ab = A + (long)z * bsA;
    const float* Bb = B + (long)z * bsB;
    float*       Cb = C + (long)z * bsC;

    const int i0 = blockIdx.y * BM;
    const int j0 = blockIdx.x * BN;
    const int tid  = threadIdx.x;
    const int warp = tid >> 5;
    const int lane = tid & 31;
    const int g = lane >> 2;
    const int t = lane & 3;
    const int wm = (warp & 3) * 32;
    const int wn = (warp >> 2) * 32;

    const bool ak1 = (ldaK == 1);
    const bool bj1 = (ldbJ == 1);

    float acc[2][4][4];
#pragma unroll
    for (int mt = 0; mt < 2; mt++)
#pragma unroll
        for (int nt = 0; nt < 4; nt++)
#pragma unroll
            for (int e = 0; e < 4; e++) acc[mt][nt][e] = 0.0f;

    float ra[8], rb[4];

    auto stage = [&](int k0) {
#pragma unroll
        for (int u = 0; u < 8; u++) {
            int e = tid + u * 256;
            int i, k;
            if (ak1) { k = e & 15; i = e >> 4; }
            else     { i = e & 127; k = e >> 7; }
            int gi = i0 + i, gk = k0 + k;
            ra[u] = (gi < M && gk < K) ? Ab[(long)gi * ldaI + (long)gk * ldaK] : 0.0f;
        }
#pragma unroll
        for (int u = 0; u < 4; u++) {
            int e = tid + u * 256;
            int n, k;
            if (bj1) { n = e & 63; k = e >> 6; }
            else     { k = e & 15; n = e >> 4; }
            int gn = j0 + n, gk = k0 + k;
            rb[u] = (gn < N && gk < K) ? Bb[(long)gk * ldbK + (long)gn * ldbJ] : 0.0f;
        }
    };
    auto commit = [&](int buf) {
#pragma unroll
        for (int u = 0; u < 8; u++) {
            int e = tid + u * 256;
            int i, k;
            if (ak1) { k = e & 15; i = e >> 4; }
            else     { i = e & 127; k = e >> 7; }
            As[buf][i][k] = f2tf32(ra[u]);
        }
#pragma unroll
        for (int u = 0; u < 4; u++) {
            int e = tid + u * 256;
            int n, k;
            if (bj1) { n = e & 63; k = e >> 6; }
            else     { k = e & 15; n = e >> 4; }
            Bs[buf][n][k] = f2tf32(rb[u]);
        }
    };

    stage(0);
    commit(0);
    __syncthreads();

    int buf = 0;
    for (int k0 = 0; k0 < K; k0 += BKT) {
        const bool more = (k0 + BKT) < K;
        if (more) stage(k0 + BKT);

#pragma unroll
        for (int kk = 0; kk < 2; kk++) {
            const int ks = kk * 8;
            u32 af[2][4], bf[4][2];
#pragma unroll
            for (int mt = 0; mt < 2; mt++) {
                int r = wm + mt * 16;
                af[mt][0] = As[buf][r + g    ][ks + t];
                af[mt][1] = As[buf][r + g + 8][ks + t];
                af[mt][2] = As[buf][r + g    ][ks + t + 4];
                af[mt][3] = As[buf][r + g + 8][ks + t + 4];
            }
#pragma unroll
            for (int nt = 0; nt < 4; nt++) {
                int c = wn + nt * 8;
                bf[nt][0] = Bs[buf][c + g][ks + t];
                bf[nt][1] = Bs[buf][c + g][ks + t + 4];
            }
#pragma unroll
            for (int mt = 0; mt < 2; mt++)
#pragma unroll
                for (int nt = 0; nt < 4; nt++)
                    mma_tf32(acc[mt][nt], af[mt], bf[nt]);
        }

        if (more) {
            commit(buf ^ 1);
            __syncthreads();
            buf ^= 1;
        }
    }

#pragma unroll
    for (int mt = 0; mt < 2; mt++) {
#pragma unroll
        for (int nt = 0; nt < 4; nt++) {
            int col = j0 + wn + nt * 8 + t * 2;
            if (col >= N) continue;
#pragma unroll
            for (int half = 0; half < 2; half++) {
                int row = i0 + wm + mt * 16 + g + half * 8;
                if (row >= M) continue;
                *(float2*)&Cb[(long)row * ldcI + col] =
                    make_float2(acc[mt][nt][half * 2 + 0], acc[mt][nt][half * 2 + 1]);
            }
        }
    }
}

// ---------------------------------------------------------------------------
__global__ void add_bias2(const float* __restrict__ src,
                          const float* __restrict__ bw,
                          const float* __restrict__ br,
                          float* __restrict__ dw, float* __restrict__ dr, long n)
{
    long idx = (long)blockIdx.x * blockDim.x + threadIdx.x;
    long stride = (long)gridDim.x * blockDim.x;
    for (; idx < n; idx += stride) {
        int c = (int)(idx & (DM - 1));
        float v = src[idx];
        dw[idx] = tf32r(v + bw[c]);
        dr[idx] = tf32r(v + br[c]);
    }
}

// ---------------------------------------------------------------------------
// Elementwise tf32 rounding (pre-round shared GEMM inputs).
// ---------------------------------------------------------------------------
__global__ void round_buf(const float* __restrict__ x, float* __restrict__ y, long n)
{
    long i = (long)blockIdx.x * blockDim.x + threadIdx.x;
    long st = (long)gridDim.x * blockDim.x;
    for (; i < n; i += st) y[i] = tf32r(x[i]);
}

// ---------------------------------------------------------------------------
// Mask transpose: MT[b][i][j] = mask[i][j][b].
// ---------------------------------------------------------------------------
__global__ void mask_t(const float* __restrict__ m, float* __restrict__ mt)
{
    const int i = blockIdx.x;
    const int b = blockIdx.y;
    const float* src = m + (long)i * KLEN * BSZ + b;
    float* dst = mt + ((long)b * QLEN + i) * KLEN;
    for (int j = threadIdx.x; j < KLEN; j += blockDim.x)
        dst[j] = src[(long)j * BSZ];
}

// ---------------------------------------------------------------------------
// Softmax with relative shift gather; mask from transposed MT. tf32 P.
// ---------------------------------------------------------------------------
__global__ void softmax_shift(const float* __restrict__ AC,
                              const float* __restrict__ BD,
                              const float* __restrict__ MTm,
                              float* __restrict__ P)
{
    const int i = blockIdx.x;
    const int z = blockIdx.y;
    const int b = z >> 4;
    const float* ac = AC + ((long)z * QLEN + i) * KLEN;
    const float* bd = BD + ((long)z * QLEN + i) * RLEN;
    const float* mk = MTm + ((long)b * QLEN + i) * KLEN;
    float*       p  = P  + ((long)z * QLEN + i) * KLEN;

    __shared__ float red[256];
    const int tid = threadIdx.x;

    float vals[4];
    float lm = -1e38f;
#pragma unroll
    for (int r = 0; r < 4; r++) {
        int j = tid + r * 256;
        float s = (ac[j] + bd[j - i + KLEN]) * 0.125f - 1e30f * mk[j];
        vals[r] = s;
        lm = fmaxf(lm, s);
    }
    red[tid] = lm; __syncthreads();
    for (int s = 128; s > 0; s >>= 1) {
        if (tid < s) red[tid] = fmaxf(red[tid], red[tid + s]);
        __syncthreads();
    }
    float mx = red[0]; __syncthreads();

    float ls = 0.0f;
#pragma unroll
    for (int r = 0; r < 4; r++) {
        vals[r] = __expf(vals[r] - mx);
        ls += vals[r];
    }
    red[tid] = ls; __syncthreads();
    for (int s = 128; s > 0; s >>= 1) {
        if (tid < s) red[tid] += red[tid + s];
        __syncthreads();
    }
    float inv = 1.0f / red[0];
#pragma unroll
    for (int r = 0; r < 4; r++)
        p[tid + r * 256] = tf32r(vals[r] * inv);
}

// ---------------------------------------------------------------------------
__global__ void ln_res(const float* __restrict__ x, const float* __restrict__ res,
                       const float* __restrict__ sc, const float* __restrict__ bi,
                       float* __restrict__ out)
{
    const long row = blockIdx.x;
    const float* xr = x   + row * DM;
    const float* rr = res + row * DM;
    float*       o  = out + row * DM;
    const int tid = threadIdx.x;

    __shared__ float red[256];

    float v[4];
    float s = 0.0f;
#pragma unroll
    for (int r = 0; r < 4; r++) {
        int c = tid + r * 256;
        v[r] = xr[c] + rr[c];
        s += v[r];
    }
    red[tid] = s; __syncthreads();
    for (int st = 128; st > 0; st >>= 1) {
        if (tid < st) red[tid] += red[tid + st];
        __syncthreads();
    }
    float mean = red[0] * (1.0f / DM); __syncthreads();

    float sq = 0.0f;
#pragma unroll
    for (int r = 0; r < 4; r++) {
        float d = v[r] - mean;
        sq += d * d;
    }
    red[tid] = sq; __syncthreads();
    for (int st = 128; st > 0; st >>= 1) {
        if (tid < st) red[tid] += red[tid + st];
        __syncthreads();
    }
    float rstd = rsqrtf(red[0] * (1.0f / DM) + 1e-8f);
#pragma unroll
    for (int r = 0; r < 4; r++) {
        int c = tid + r * 256;
        o[c] = (v[r] - mean) * rstd * sc[c] + bi[c];
    }
}

// ---------------------------------------------------------------------------
template<int TBN, int BTR, int CVA, int CVB>
static void launchG(const float* A, const float* B, float* C,
                    int M, int N, int K,
                    long ldaI, long bsA, long ldb, long bsB,
                    long ldcI, long bsC,
                    const float* bias, int act, int nb,
                    int diagskip = 0, int rndC = 0,
                    float* C2 = nullptr, const float* bias2 = nullptr)
{
    constexpr int BSTR = BTR ? (TBN + 8) : SK2;
    constexpr int SMEM = (3 * 128 * SK2 + 3 * (BTR ? 32 * BSTR : TBN * SK2)) * 4;
    cudaFuncSetAttribute(gemm_fast<TBN, BTR, CVA, CVB>,
                         cudaFuncAttributeMaxDynamicSharedMemorySize, SMEM);
    gemm_fast<TBN, BTR, CVA, CVB><<<dim3(N / TBN, M / 128, nb), 256, SMEM>>>(
        A, B, C, K, ldaI, bsA, ldb, bsB, ldcI, bsC, bias, act, diagskip, rndC, C2, bias2);
}

extern "C" void kernel_launch(void* const* d_in, const int* in_sizes, int n_in,
                              void* d_out, int out_size)
{
    const float* Xh  = (const float*)d_in[0];
    const float* Xg  = (const float*)d_in[1];
    const float* mh  = (const float*)d_in[2];
    const float* mg  = (const float*)d_in[3];
    const float* R   = (const float*)d_in[4];
    const float* TM  = (const float*)d_in[5];
    const float* qw  = (const float*)d_in[6];
    const float* kw  = (const float*)d_in[7];
    const float* vw  = (const float*)d_in[8];
    const float* rw  = (const float*)d_in[9];
    const float* rrb = (const float*)d_in[10];
    const float* rwb = (const float*)d_in[11];
    const float* lns = (const float*)d_in[12];
    const float* lnb = (const float*)d_in[13];
    const float* w1  = (const float*)d_in[14];
    const float* b1  = (const float*)d_in[15];
    const float* w2  = (const float*)d_in[16];
    const float* b2  = (const float*)d_in[17];
    const float* fls = (const float*)d_in[18];
    const float* flb = (const float*)d_in[19];
    float* out = (float*)d_out;

    float *KH, *VH, *KR, *QT, *QW, *QR, *QG, *AC, *BD, *MTp, *AV, *AV2,
          *ATTH, *ATTG, *FF1, *FF2;
    cudaGetSymbolAddress((void**)&KH,  g_KH);
    cudaGetSymbolAddress((void**)&VH,  g_VH);
    cudaGetSymbolAddress((void**)&KR,  g_KR);
    cudaGetSymbolAddress((void**)&QT,  g_QT);
    cudaGetSymbolAddress((void**)&QW,  g_QW);
    cudaGetSymbolAddress((void**)&QR,  g_QR);
    cudaGetSymbolAddress((void**)&QG,  g_QG);
    cudaGetSymbolAddress((void**)&AC,  g_AC);
    cudaGetSymbolAddress((void**)&BD,  g_BD);
    cudaGetSymbolAddress((void**)&MTp, g_MT);
    cudaGetSymbolAddress((void**)&AV,  g_AV);
    cudaGetSymbolAddress((void**)&AV2, g_AV2);
    cudaGetSymbolAddress((void**)&ATTH, g_ATTH);
    cudaGetSymbolAddress((void**)&ATTG, g_ATTG);
    cudaGetSymbolAddress((void**)&FF1, g_FF1);
    cudaGetSymbolAddress((void**)&FF2, g_FF2);

    const int T = 256;
    const int MH = QLEN * BSZ;     // 4096
    const int MG = NPRED * BSZ;    // 1024

    // ---- pre-round Xh (reused by K/V/Q projections; QT free until g-stream) ----
    round_buf<<<4096, T>>>(Xh, QT, (long)MH * DM);

    // ---- shared projections ----
    launchG<128,1,0,1>(QT, kw, KH, MH, DM, DM, DM, 0, DM, 0, DM, 0, nullptr, 0, 1, 0, 1);
    launchG<128,1,0,1>(QT, vw, VH, MH, DM, DM, DM, 0, DM, 0, DM, 0, nullptr, 0, 1, 0, 1);
    launchG<128,1,1,1>(R,  rw, KR, RLEN * BSZ, DM, DM, DM, 0, DM, 0, DM, 0, nullptr, 0, 1, 0, 1);

    // ================= h-stream =================
    launchG<128,1,0,1>(QT, qw, QW, MH, DM, DM, DM, 0, DM, 0, DM, 0, rwb, 0, 1, 0, 1, QR, rrb);

    launchG<128,0,0,0>(QW, KH, AC, QLEN, KLEN, DH, 4096, 64, 4096, 64,
                   KLEN, (long)QLEN * KLEN, nullptr, 0, NB);
    launchG<128,0,0,0>(QR, KR, BD, QLEN, RLEN, DH, 4096, 64, 4096, 64,
                   RLEN, (long)QLEN * RLEN, nullptr, 0, NB, 1);
    mask_t<<<dim3(QLEN, BSZ), T>>>(mh, MTp);
    softmax_shift<<<dim3(QLEN, NB), T>>>(AC, BD, MTp, AC);
    launchG<64,1,0,0>(AC, VH, AV, QLEN, DH, KLEN, KLEN, (long)QLEN * KLEN,
                  4096, 64, 4096, 64, nullptr, 0, NB);
    ln_res<<<MH, T>>>(AV, Xh, lns, lnb, ATTH);

    // ================= g-stream =================
    launchG<128,1,1,1>(Xg, qw, QG, MG, DM, DM, DM, 0, DM, 0, DM, 0, nullptr, 0, 1);
    bgemm_tc<<<dim3(DM / BN, QLEN / BM, BSZ), T>>>(TM, QG, QT, QLEN, DM, NPRED,
              4, 4096, 1,   4096, 1, DM,   4096, DM);
    add_bias2<<<4096, T>>>(QT, rwb, rrb, QW, QR, (long)MH * DM);

    launchG<128,0,0,0>(QW, KH, AC, QLEN, KLEN, DH, 4096, 64, 4096, 64,
                   KLEN, (long)QLEN * KLEN, nullptr, 0, NB);
    launchG<128,0,0,0>(QR, KR, BD, QLEN, RLEN, DH, 4096, 64, 4096, 64,
                   RLEN, (long)QLEN * RLEN, nullptr, 0, NB, 1);
    mask_t<<<dim3(QLEN, BSZ), T>>>(mg, MTp);
    softmax_shift<<<dim3(QLEN, NB), T>>>(AC, BD, MTp, AC);
    launchG<64,1,0,0>(AC, VH, AV, QLEN, DH, KLEN, KLEN, (long)QLEN * KLEN,
                  4096, 64, 4096, 64, nullptr, 0, NB);
    bgemm_tc<<<dim3(DM / BN, NPRED / BM, BSZ), T>>>(TM, AV, AV2, NPRED, DM, QLEN,
              4096, 4, 1,   4096, 1, DM,   4096, DM);
    ln_res<<<MG, T>>>(AV2, Xg, lns, lnb, ATTG);

    // ================= FFN (h) =================
    launchG<128,1,1,1>(ATTH, w1, FF1, MH, DI, DM, DM, 0, DI, 0, DI, 0, b1, 1, 1, 0, 1);
    launchG<128,1,0,1>(FF1, w2, FF2, MH, DM, DI, DI, 0, DM, 0, DM, 0, b2, 0, 1);
    ln_res<<<MH, T>>>(FF2, ATTH, fls, flb, out);

    // ================= FFN (g) =================
    launchG<128,1,1,1>(ATTG, w1, FF1, MG, DI, DM, DM, 0, DI, 0, DI, 0, b1, 1, 1, 0, 1);
    launchG<128,1,0,1>(FF1, w2, FF2, MG, DM, DI, DI, 0, DM, 0, DM, 0, b2, 0, 1);
    ln_res<<<MG, T>>>(FF2, ATTG, fls, flb, out + (long)MH * DM);
}

// round 15
// speedup vs baseline: 1.2274x; 1.0004x over previous
#include <cuda_runtime.h>
#include <cstdint>
#include <math.h>

#define QLEN  1024
#define KLEN  1024
#define RLEN  2048
#define NPRED 256
#define BSZ   4
#define NH    16
#define DH    64
#define DM    1024
#define DI    4096
#define NB    (BSZ*NH)   /* 64 head-batches */

typedef unsigned int u32;

// ---------------------------------------------------------------------------
// Scratch (device globals; allocation in kernel_launch is forbidden)
// ---------------------------------------------------------------------------
__device__ float g_KH [QLEN*BSZ*DM];
__device__ float g_VH [QLEN*BSZ*DM];
__device__ float g_KR [RLEN*BSZ*DM];
__device__ float g_QT [QLEN*BSZ*DM];    // XhT (early) / target-mapping temp (late)
__device__ float g_QW [QLEN*BSZ*DM];
__device__ float g_QR [QLEN*BSZ*DM];
__device__ float g_QG [NPRED*BSZ*DM];
__device__ float g_AC [(long)NB*QLEN*KLEN];
__device__ float g_BD [(long)NB*QLEN*RLEN];
__device__ float g_MT [(long)BSZ*QLEN*KLEN];   // transposed mask [b][i][j]
__device__ float g_AV [QLEN*BSZ*DM];
__device__ float g_AV2[NPRED*BSZ*DM];
__device__ float g_ATTH[QLEN*BSZ*DM];
__device__ float g_ATTG[NPRED*BSZ*DM];
__device__ float g_FF1[QLEN*BSZ*DI];
__device__ float g_FF2[QLEN*BSZ*DM];

// ---------------------------------------------------------------------------
__device__ __forceinline__ u32 f2tf32(float v)
{
    u32 r;
    asm("cvt.rna.tf32.f32 %0, %1;" : "=r"(r) : "f"(v));
    return r;
}
__device__ __forceinline__ u32 cvtu(u32 raw)
{
    u32 r;
    asm("cvt.rna.tf32.f32 %0, %1;" : "=r"(r) : "f"(__uint_as_float(raw)));
    return r;
}
__device__ __forceinline__ float tf32r(float v)
{
    return __uint_as_float(f2tf32(v));
}

__device__ __forceinline__ void mma_tf32(float* c, const u32* a, const u32* b)
{
    asm volatile(
        "mma.sync.aligned.m16n8k8.row.col.f32.tf32.tf32.f32 "
        "{%0,%1,%2,%3}, {%4,%5,%6,%7}, {%8,%9}, {%0,%1,%2,%3};\n"
        : "+f"(c[0]), "+f"(c[1]), "+f"(c[2]), "+f"(c[3])
        : "r"(a[0]), "r"(a[1]), "r"(a[2]), "r"(a[3]), "r"(b[0]), "r"(b[1]));
}

__device__ __forceinline__ void ldsm4(u32& r0, u32& r1, u32& r2, u32& r3, u32 addr)
{
    asm volatile(
        "ldmatrix.sync.aligned.m8n8.x4.shared.b16 {%0,%1,%2,%3}, [%4];\n"
        : "=r"(r0), "=r"(r1), "=r"(r2), "=r"(r3) : "r"(addr));
}

__device__ __forceinline__ void cpa16(u32 saddr, const void* gaddr)
{
    asm volatile("cp.async.cg.shared.global [%0], [%1], 16;\n"
                 :: "r"(saddr), "l"(gaddr));
}
__device__ __forceinline__ void cpa_commit() { asm volatile("cp.async.commit_group;\n"); }
__device__ __forceinline__ void cpa_wait1()  { asm volatile("cp.async.wait_group 1;\n"); }

// ===========================================================================
// FAST GEMM, BK=32. A k-contiguous, M%128==0, K%32==0, N%TBN==0.
//   BTR=1: B n-contiguous. BTR=0: B k-contiguous.
//   CVA/CVB: tf32-convert at fragment load (0 when producer stored
//   tf32-rounded values — bit-identical results).
// 3-stage cp.async pipeline, 128 x TBN tile, 256 threads.
// ===========================================================================
#define SK2 36   /* A / B(ldsm) smem row stride in u32 (32 + 4 pad) */

template<int TBN, int BTR, int CVA, int CVB>
__global__ __launch_bounds__(256, 2) void gemm_fast(
    const float* __restrict__ A, const float* __restrict__ B,
    float* __restrict__ C, int K,
    long ldaI, long bsA,
    long ldb,  long bsB,
    long ldcI, long bsC,
    const float* __restrict__ bias, int act, int diagskip, int rndC,
    float* __restrict__ C2, const float* __restrict__ bias2)
{
    constexpr int WARPS_M = (TBN == 128) ? 2 : 4;
    constexpr int MT      = (128 / WARPS_M) / 16;     // 4 / 2
    constexpr int NT      = 4;
    constexpr int NCHB    = TBN / 32;                 // B cp.async per thread
    constexpr int BSTR    = BTR ? (TBN + 8) : SK2;
    constexpr int ABUF    = 128 * SK2 * 4;            // 18432 B per stage
    constexpr int BBUF    = (BTR ? 32 * BSTR : TBN * SK2) * 4;

    extern __shared__ __align__(16) u32 dyn[];
    u32* Asp = dyn;
    u32* Bsp = dyn + 3 * 128 * SK2;

    const int i0 = blockIdx.y * 128;
    const int j0 = blockIdx.x * TBN;
    if (diagskip && (i0 + j0 < 770 || i0 + j0 > 2047)) return;

    const int z = blockIdx.z;
    const float* Ab = A + (long)z * bsA;
    const float* Bb = B + (long)z * bsB;
    float*       Cb = C + (long)z * bsC;

    const int tid  = threadIdx.x;
    const int warp = tid >> 5;
    const int lane = tid & 31;
    const int g = lane >> 2;
    const int t = lane & 3;
    const int wm = (warp % WARPS_M) * (128 / WARPS_M);
    const int wn = (warp / WARPS_M) * 32;

    const u32 sa_base = (u32)__cvta_generic_to_shared(Asp);
    const u32 sb_base = (u32)__cvta_generic_to_shared(Bsp);

    const int mi = lane >> 3;
    const int ri = lane & 7;
    u32 aoff[MT];
#pragma unroll
    for (int mt = 0; mt < MT; mt++)
        aoff[mt] = ((u32)(wm + mt * 16 + (mi & 1) * 8 + ri) * SK2 + (u32)(mi >> 1) * 4) * 4;
    u32 boff[2];
#pragma unroll
    for (int p = 0; p < 2; p++)
        boff[p] = ((u32)(wn + p * 16 + (mi >> 1) * 8 + ri) * SK2 + (u32)(mi & 1) * 4) * 4;

    // ---- A staging: 128 rows x 32 floats, 4 cpa16 per thread ----
    u32 sAo[4];
    const float* gA[4];
#pragma unroll
    for (int u = 0; u < 4; u++) {
        int idx = tid + 256 * u;
        int row = idx >> 3, q4 = (idx & 7) * 4;
        sAo[u] = ((u32)row * SK2 + q4) * 4;
        gA[u]  = Ab + (long)(i0 + row) * ldaI + q4;
    }

    // ---- B staging ----
    u32 sBo[NCHB];
    const float* gB[NCHB];
    long bstep;
    if (BTR) {
        bstep = 32 * ldb;
#pragma unroll
        for (int u = 0; u < NCHB; u++) {
            int idx = tid + 256 * u;
            int k  = idx / (TBN / 4);
            int n4 = (idx % (TBN / 4)) * 4;
            sBo[u] = ((u32)k * BSTR + n4) * 4;
            gB[u]  = Bb + (long)k * ldb + (j0 + n4);
        }
    } else {
        bstep = 32;
#pragma unroll
        for (int u = 0; u < NCHB; u++) {
            int idx = tid + 256 * u;
            int row = idx >> 3, q4 = (idx & 7) * 4;
            sBo[u] = ((u32)row * SK2 + q4) * 4;
            gB[u]  = Bb + (long)(j0 + row) * ldb + q4;
        }
    }

    const int nk = K >> 5;   // BK = 32

    auto issue = [&](int stage, int it) {
        u32 ab = sa_base + (u32)stage * ABUF;
        u32 bb = sb_base + (u32)stage * BBUF;
        long ka = (long)it * 32;
        long kb = (long)it * bstep;
#pragma unroll
        for (int u = 0; u < 4; u++)
            cpa16(ab + sAo[u], gA[u] + ka);
#pragma unroll
        for (int u = 0; u < NCHB; u++)
            cpa16(bb + sBo[u], gB[u] + kb);
    };

    float acc[MT][NT][4];
#pragma unroll
    for (int mt = 0; mt < MT; mt++)
#pragma unroll
        for (int nt = 0; nt < NT; nt++)
#pragma unroll
            for (int e = 0; e < 4; e++) acc[mt][nt][e] = 0.0f;

    issue(0, 0); cpa_commit();
    if (nk > 1) issue(1, 1);
    cpa_commit();

    int buf = 0;
    for (int it = 0; it < nk; it++) {
        cpa_wait1();
        __syncthreads();

        const u32 ab = sa_base + (u32)buf * ABUF;
        const u32 bb = sb_base + (u32)buf * BBUF;
        const u32* Brow = Bsp + buf * (BBUF / 4);

#pragma unroll
        for (int kk = 0; kk < 4; kk++) {
            const u32 ksb = kk * 32;   // 8 k * 4 B
            const int ks  = kk * 8;
            u32 af[MT][4], bf2[2][4];
#pragma unroll
            for (int mt = 0; mt < MT; mt++) {
                ldsm4(af[mt][0], af[mt][1], af[mt][2], af[mt][3], ab + aoff[mt] + ksb);
                if (CVA) {
                    af[mt][0] = cvtu(af[mt][0]); af[mt][1] = cvtu(af[mt][1]);
                    af[mt][2] = cvtu(af[mt][2]); af[mt][3] = cvtu(af[mt][3]);
                }
            }
            if (BTR) {
#pragma unroll
                for (int p = 0; p < 2; p++) {
                    int c = wn + p * 16;
                    bf2[p][0] = Brow[(ks + t) * BSTR + c + g];
                    bf2[p][1] = Brow[(ks + t + 4) * BSTR + c + g];
                    bf2[p][2] = Brow[(ks + t) * BSTR + c + 8 + g];
                    bf2[p][3] = Brow[(ks + t + 4) * BSTR + c + 8 + g];
                    if (CVB) {
                        bf2[p][0] = cvtu(bf2[p][0]); bf2[p][1] = cvtu(bf2[p][1]);
                        bf2[p][2] = cvtu(bf2[p][2]); bf2[p][3] = cvtu(bf2[p][3]);
                    }
                }
            } else {
#pragma unroll
                for (int p = 0; p < 2; p++) {
                    ldsm4(bf2[p][0], bf2[p][1], bf2[p][2], bf2[p][3], bb + boff[p] + ksb);
                    if (CVB) {
                        bf2[p][0] = cvtu(bf2[p][0]); bf2[p][1] = cvtu(bf2[p][1]);
                        bf2[p][2] = cvtu(bf2[p][2]); bf2[p][3] = cvtu(bf2[p][3]);
                    }
                }
            }
#pragma unroll
            for (int mt = 0; mt < MT; mt++)
#pragma unroll
                for (int nt = 0; nt < NT; nt++)
                    mma_tf32(acc[mt][nt], af[mt], &bf2[nt >> 1][(nt & 1) * 2]);
        }

        int ns = it + 2;
        if (ns < nk) issue(ns % 3, ns);
        cpa_commit();
        buf = (buf == 2) ? 0 : buf + 1;
    }

    // epilogue
#pragma unroll
    for (int mt = 0; mt < MT; mt++) {
#pragma unroll
        for (int nt = 0; nt < NT; nt++) {
            int col = j0 + wn + nt * 8 + t * 2;
            float b0 = 0.0f, b1 = 0.0f;
            if (bias) { b0 = bias[col]; b1 = bias[col + 1]; }
            float c0 = 0.0f, c1 = 0.0f;
            if (C2) { c0 = bias2[col]; c1 = bias2[col + 1]; }
#pragma unroll
            for (int half = 0; half < 2; half++) {
                int row = i0 + wm + mt * 16 + g + half * 8;
                float a0 = acc[mt][nt][half * 2 + 0];
                float a1 = acc[mt][nt][half * 2 + 1];
                float v0 = a0 + b0, v1 = a1 + b1;
                if (act) {
                    v0 = 0.5f * v0 * (1.0f + erff(v0 * 0.70710678118654752f));
                    v1 = 0.5f * v1 * (1.0f + erff(v1 * 0.70710678118654752f));
                }
                if (rndC) { v0 = tf32r(v0); v1 = tf32r(v1); }
                *(float2*)&Cb[(long)row * ldcI + col] = make_float2(v0, v1);
                if (C2) {
                    float w0 = a0 + c0, w1 = a1 + c1;
                    if (rndC) { w0 = tf32r(w0); w1 = tf32r(w1); }
                    *(float2*)&C2[(long)row * ldcI + col] = make_float2(w0, w1);
                }
            }
        }
    }
}

// ===========================================================================
// Generic fallback — used only for the two target-mapping GEMMs.
// ===========================================================================
#define BM 128
#define BN 64
#define BKT 16

__global__ __launch_bounds__(256) void bgemm_tc(
    const float* __restrict__ A, const float* __restrict__ B,
    float* __restrict__ C,
    int M, int N, int K,
    long ldaI, long ldaK, long bsA,
    long ldbK, long ldbJ, long bsB,
    long ldcI, long bsC)
{
    __shared__ u32 As[2][BM][BKT + 1];
    __shared__ u32 Bs[2][BN][BKT + 1];

    const int z = blockIdx.z;
    const float* Ab = A + (long)z * bsA;
    const float* Bb = B + (long)z * bsB;
    float*       Cb = C + (long)z * bsC;

    const int i0 = blockIdx.y * BM;
    const int j0 = blockIdx.x * BN;
    const int tid  = threadIdx.x;
    const int warp = tid >> 5;
    const int lane = tid & 31;
    const int g = lane >> 2;
    const int t = lane & 3;
    const int wm = (warp & 3) * 32;
    const int wn = (warp >> 2) * 32;

    const bool ak1 = (ldaK == 1);
    const bool bj1 = (ldbJ == 1);

    float acc[2][4][4];
#pragma unroll
    for (int mt = 0; mt < 2; mt++)
#pragma unroll
        for (int nt = 0; nt < 4; nt++)
#pragma unroll
            for (int e = 0; e < 4; e++) acc[mt][nt][e] = 0.0f;

    float ra[8], rb[4];

    auto stage = [&](int k0) {
#pragma unroll
        for (int u = 0; u < 8; u++) {
            int e = tid + u * 256;
            int i, k;
            if (ak1) { k = e & 15; i = e >> 4; }
            else     { i = e & 127; k = e >> 7; }
            int gi = i0 + i, gk = k0 + k;
            ra[u] = (gi < M && gk < K) ? Ab[(long)gi * ldaI + (long)gk * ldaK] : 0.0f;
        }
#pragma unroll
        for (int u = 0; u < 4; u++) {
            int e = tid + u * 256;
            int n, k;
            if (bj1) { n = e & 63; k = e >> 6; }
            else     { k = e & 15; n = e >> 4; }
            int gn = j0 + n, gk = k0 + k;
            rb[u] = (gn < N && gk < K) ? Bb[(long)gk * ldbK + (long)gn * ldbJ] : 0.0f;
        }
    };
    auto commit = [&](int buf) {
#pragma unroll
        for (int u = 0; u < 8; u++) {
            int e = tid + u * 256;
            int i, k;
            if (ak1) { k = e & 15; i = e >> 4; }
            else     { i = e & 127; k = e >> 7; }
            As[buf][i][k] = f2tf32(ra[u]);
        }
#pragma unroll
        for (int u = 0; u < 4; u++) {
            int e = tid + u * 256;
            int n, k;
            if (bj1) { n = e & 63; k = e >> 6; }
            else     { k = e & 15; n = e >> 4; }
            Bs[buf][n][k] = f2tf32(rb[u]);
        }
    };

    stage(0);
    commit(0);
    __syncthreads();

    int buf = 0;
    for (int k0 = 0; k0 < K; k0 += BKT) {
        const bool more = (k0 + BKT) < K;
        if (more) stage(k0 + BKT);

#pragma unroll
        for (int kk = 0; kk < 2; kk++) {
            const int ks = kk * 8;
            u32 af[2][4], bf[4][2];
#pragma unroll
            for (int mt = 0; mt < 2; mt++) {
                int r = wm + mt * 16;
                af[mt][0] = As[buf][r + g    ][ks + t];
                af[mt][1] = As[buf][r + g + 8][ks + t];
                af[mt][2] = As[buf][r + g    ][ks + t + 4];
                af[mt][3] = As[buf][r + g + 8][ks + t + 4];
            }
#pragma unroll
            for (int nt = 0; nt < 4; nt++) {
                int c = wn + nt * 8;
                bf[nt][0] = Bs[buf][c + g][ks + t];
                bf[nt][1] = Bs[buf][c + g][ks + t + 4];
            }
#pragma unroll
            for (int mt = 0; mt < 2; mt++)
#pragma unroll
                for (int nt = 0; nt < 4; nt++)
                    mma_tf32(acc[mt][nt], af[mt], bf[nt]);
        }

        if (more) {
            commit(buf ^ 1);
            __syncthreads();
            buf ^= 1;
        }
    }

#pragma unroll
    for (int mt = 0; mt < 2; mt++) {
#pragma unroll
        for (int nt = 0; nt < 4; nt++) {
            int col = j0 + wn + nt * 8 + t * 2;
            if (col >= N) continue;
#pragma unroll
            for (int half = 0; half < 2; half++) {
                int row = i0 + wm + mt * 16 + g + half * 8;
                if (row >= M) continue;
                *(float2*)&Cb[(long)row * ldcI + col] =
                    make_float2(acc[mt][nt][half * 2 + 0], acc[mt][nt][half * 2 + 1]);
            }
        }
    }
}

// ---------------------------------------------------------------------------
__global__ void add_bias2(const float* __restrict__ src,
                          const float* __restrict__ bw,
                          const float* __restrict__ br,
                          float* __restrict__ dw, float* __restrict__ dr, long n)
{
    long idx = (long)blockIdx.x * blockDim.x + threadIdx.x;
    long stride = (long)gridDim.x * blockDim.x;
    for (; idx < n; idx += stride) {
        int c = (int)(idx & (DM - 1));
        float v = src[idx];
        dw[idx] = tf32r(v + bw[c]);
        dr[idx] = tf32r(v + br[c]);
    }
}

// ---------------------------------------------------------------------------
// Elementwise tf32 rounding (pre-round shared GEMM inputs).
// ---------------------------------------------------------------------------
__global__ void round_buf(const float* __restrict__ x, float* __restrict__ y, long n)
{
    long i = (long)blockIdx.x * blockDim.x + threadIdx.x;
    long st = (long)gridDim.x * blockDim.x;
    for (; i < n; i += st) y[i] = tf32r(x[i]);
}

// ---------------------------------------------------------------------------
// Mask transpose: MT[b][i][j] = mask[i][j][b].
// ---------------------------------------------------------------------------
__global__ void mask_t(const float* __restrict__ m, float* __restrict__ mt)
{
    const int i = blockIdx.x;
    const int b = blockIdx.y;
    const float* src = m + (long)i * KLEN * BSZ + b;
    float* dst = mt + ((long)b * QLEN + i) * KLEN;
    for (int j = threadIdx.x; j < KLEN; j += blockDim.x)
        dst[j] = src[(long)j * BSZ];
}

// ---------------------------------------------------------------------------
// Softmax with relative shift gather; mask from transposed MT. tf32 P.
// ---------------------------------------------------------------------------
__global__ void softmax_shift(const float* __restrict__ AC,
                              const float* __restrict__ BD,
                              const float* __restrict__ MTm,
                              float* __restrict__ P)
{
    const int i = blockIdx.x;
    const int z = blockIdx.y;
    const int b = z >> 4;
    const float* ac = AC + ((long)z * QLEN + i) * KLEN;
    const float* bd = BD + ((long)z * QLEN + i) * RLEN;
    const float* mk = MTm + ((long)b * QLEN + i) * KLEN;
    float*       p  = P  + ((long)z * QLEN + i) * KLEN;

    __shared__ float red[256];
    const int tid = threadIdx.x;

    float vals[4];
    float lm = -1e38f;
#pragma unroll
    for (int r = 0; r < 4; r++) {
        int j = tid + r * 256;
        float s = (ac[j] + bd[j - i + KLEN]) * 0.125f - 1e30f * mk[j];
        vals[r] = s;
        lm = fmaxf(lm, s);
    }
    red[tid] = lm; __syncthreads();
    for (int s = 128; s > 0; s >>= 1) {
        if (tid < s) red[tid] = fmaxf(red[tid], red[tid + s]);
        __syncthreads();
    }
    float mx = red[0]; __syncthreads();

    float ls = 0.0f;
#pragma unroll
    for (int r = 0; r < 4; r++) {
        vals[r] = __expf(vals[r] - mx);
        ls += vals[r];
    }
    red[tid] = ls; __syncthreads();
    for (int s = 128; s > 0; s >>= 1) {
        if (tid < s) red[tid] += red[tid + s];
        __syncthreads();
    }
    float inv = 1.0f / red[0];
#pragma unroll
    for (int r = 0; r < 4; r++)
        p[tid + r * 256] = tf32r(vals[r] * inv);
}

// ---------------------------------------------------------------------------
__global__ void ln_res(const float* __restrict__ x, const float* __restrict__ res,
                       const float* __restrict__ sc, const float* __restrict__ bi,
                       float* __restrict__ out)
{
    const long row = blockIdx.x;
    const float* xr = x   + row * DM;
    const float* rr = res + row * DM;
    float*       o  = out + row * DM;
    const int tid = threadIdx.x;

    __shared__ float red[256];

    float v[4];
    float s = 0.0f;
#pragma unroll
    for (int r = 0; r < 4; r++) {
        int c = tid + r * 256;
        v[r] = xr[c] + rr[c];
        s += v[r];
    }
    red[tid] = s; __syncthreads();
    for (int st = 128; st > 0; st >>= 1) {
        if (tid < st) red[tid] += red[tid + st];
        __syncthreads();
    }
    float mean = red[0] * (1.0f / DM); __syncthreads();

    float sq = 0.0f;
#pragma unroll
    for (int r = 0; r < 4; r++) {
        float d = v[r] - mean;
        sq += d * d;
    }
    red[tid] = sq; __syncthreads();
    for (int st = 128; st > 0; st >>= 1) {
        if (tid < st) red[tid] += red[tid + st];
        __syncthreads();
    }
    float rstd = rsqrtf(red[0] * (1.0f / DM) + 1e-8f);
#pragma unroll
    for (int r = 0; r < 4; r++) {
        int c = tid + r * 256;
        o[c] = (v[r] - mean) * rstd * sc[c] + bi[c];
    }
}

// ---------------------------------------------------------------------------
template<int TBN, int BTR, int CVA, int CVB>
static void launchG(const float* A, const float* B, float* C,
                    int M, int N, int K,
                    long ldaI, long bsA, long ldb, long bsB,
                    long ldcI, long bsC,
                    const float* bias, int act, int nb,
                    int diagskip = 0, int rndC = 0,
                    float* C2 = nullptr, const float* bias2 = nullptr)
{
    constexpr int BSTR = BTR ? (TBN + 8) : SK2;
    constexpr int SMEM = (3 * 128 * SK2 + 3 * (BTR ? 32 * BSTR : TBN * SK2)) * 4;
    cudaFuncSetAttribute(gemm_fast<TBN, BTR, CVA, CVB>,
                         cudaFuncAttributeMaxDynamicSharedMemorySize, SMEM);
    gemm_fast<TBN, BTR, CVA, CVB><<<dim3(N / TBN, M / 128, nb), 256, SMEM>>>(
        A, B, C, K, ldaI, bsA, ldb, bsB, ldcI, bsC, bias, act, diagskip, rndC, C2, bias2);
}

extern "C" void kernel_launch(void* const* d_in, const int* in_sizes, int n_in,
                              void* d_out, int out_size)
{
    const float* Xh  = (const float*)d_in[0];
    const float* Xg  = (const float*)d_in[1];
    const float* mh  = (const float*)d_in[2];
    const float* mg  = (const float*)d_in[3];
    const float* R   = (const float*)d_in[4];
    const float* TM  = (const float*)d_in[5];
    const float* qw  = (const float*)d_in[6];
    const float* kw  = (const float*)d_in[7];
    const float* vw  = (const float*)d_in[8];
    const float* rw  = (const float*)d_in[9];
    const float* rrb = (const float*)d_in[10];
    const float* rwb = (const float*)d_in[11];
    const float* lns = (const float*)d_in[12];
    const float* lnb = (const float*)d_in[13];
    const float* w1  = (const float*)d_in[14];
    const float* b1  = (const float*)d_in[15];
    const float* w2  = (const float*)d_in[16];
    const float* b2  = (const float*)d_in[17];
    const float* fls = (const float*)d_in[18];
    const float* flb = (const float*)d_in[19];
    float* out = (float*)d_out;

    float *KH, *VH, *KR, *QT, *QW, *QR, *QG, *AC, *BD, *MTp, *AV, *AV2,
          *ATTH, *ATTG, *FF1, *FF2;
    cudaGetSymbolAddress((void**)&KH,  g_KH);
    cudaGetSymbolAddress((void**)&VH,  g_VH);
    cudaGetSymbolAddress((void**)&KR,  g_KR);
    cudaGetSymbolAddress((void**)&QT,  g_QT);
    cudaGetSymbolAddress((void**)&QW,  g_QW);
    cudaGetSymbolAddress((void**)&QR,  g_QR);
    cudaGetSymbolAddress((void**)&QG,  g_QG);
    cudaGetSymbolAddress((void**)&AC,  g_AC);
    cudaGetSymbolAddress((void**)&BD,  g_BD);
    cudaGetSymbolAddress((void**)&MTp, g_MT);
    cudaGetSymbolAddress((void**)&AV,  g_AV);
    cudaGetSymbolAddress((void**)&AV2, g_AV2);
    cudaGetSymbolAddress((void**)&ATTH, g_ATTH);
    cudaGetSymbolAddress((void**)&ATTG, g_ATTG);
    cudaGetSymbolAddress((void**)&FF1, g_FF1);
    cudaGetSymbolAddress((void**)&FF2, g_FF2);

    const int T = 256;
    const int MH = QLEN * BSZ;     // 4096
    const int MG = NPRED * BSZ;    // 1024

    // ---- pre-round Xh (reused by K/V/Q projections; QT free until g-stream) ----
    round_buf<<<4096, T>>>(Xh, QT, (long)MH * DM);

    // ---- shared projections ----
    launchG<128,1,0,1>(QT, kw, KH, MH, DM, DM, DM, 0, DM, 0, DM, 0, nullptr, 0, 1, 0, 1);
    launchG<128,1,0,1>(QT, vw, VH, MH, DM, DM, DM, 0, DM, 0, DM, 0, nullptr, 0, 1, 0, 1);
    launchG<128,1,1,1>(R,  rw, KR, RLEN * BSZ, DM, DM, DM, 0, DM, 0, DM, 0, nullptr, 0, 1, 0, 1);

    // ================= h-stream =================
    launchG<128,1,0,1>(QT, qw, QW, MH, DM, DM, DM, 0, DM, 0, DM, 0, rwb, 0, 1, 0, 1, QR, rrb);

    launchG<128,0,0,0>(QW, KH, AC, QLEN, KLEN, DH, 4096, 64, 4096, 64,
                   KLEN, (long)QLEN * KLEN, nullptr, 0, NB);
    launchG<128,0,0,0>(QR, KR, BD, QLEN, RLEN, DH, 4096, 64, 4096, 64,
                   RLEN, (long)QLEN * RLEN, nullptr, 0, NB, 1);
    mask_t<<<dim3(QLEN, BSZ), T>>>(mh, MTp);
    softmax_shift<<<dim3(QLEN, NB), T>>>(AC, BD, MTp, AC);
    launchG<64,1,0,0>(AC, VH, AV, QLEN, DH, KLEN, KLEN, (long)QLEN * KLEN,
                  4096, 64, 4096, 64, nullptr, 0, NB);
    ln_res<<<MH, T>>>(AV, Xh, lns, lnb, ATTH);

    // ================= g-stream =================
    launchG<128,1,1,1>(Xg, qw, QG, MG, DM, DM, DM, 0, DM, 0, DM, 0, nullptr, 0, 1);
    bgemm_tc<<<dim3(DM / BN, QLEN / BM, BSZ), T>>>(TM, QG, QT, QLEN, DM, NPRED,
              4, 4096, 1,   4096, 1, DM,   4096, DM);
    add_bias2<<<4096, T>>>(QT, rwb, rrb, QW, QR, (long)MH * DM);

    launchG<128,0,0,0>(QW, KH, AC, QLEN, KLEN, DH, 4096, 64, 4096, 64,
                   KLEN, (long)QLEN * KLEN, nullptr, 0, NB);
    launchG<128,0,0,0>(QR, KR, BD, QLEN, RLEN, DH, 4096, 64, 4096, 64,
                   RLEN, (long)QLEN * RLEN, nullptr, 0, NB, 1);
    mask_t<<<dim3(QLEN, BSZ), T>>>(mg, MTp);
    softmax_shift<<<dim3(QLEN, NB), T>>>(AC, BD, MTp, AC);
    launchG<64,1,0,0>(AC, VH, AV, QLEN, DH, KLEN, KLEN, (long)QLEN * KLEN,
                  4096, 64, 4096, 64, nullptr, 0, NB);
    bgemm_tc<<<dim3(DM / BN, NPRED / BM, BSZ), T>>>(TM, AV, AV2, NPRED, DM, QLEN,
              4096, 4, 1,   4096, 1, DM,   4096, DM);
    ln_res<<<MG, T>>>(AV2, Xg, lns, lnb, ATTG);

    // ================= FFN (h) =================
    launchG<128,1,1,1>(ATTH, w1, FF1, MH, DI, DM, DM, 0, DI, 0, DI, 0, b1, 1, 1, 0, 1);
    launchG<128,1,0,1>(FF1, w2, FF2, MH, DM, DI, DI, 0, DM, 0, DM, 0, b2, 0, 1);
    ln_res<<<MH, T>>>(FF2, ATTH, fls, flb, out);

    // ================= FFN (g) =================
    launchG<128,1,1,1>(ATTG, w1, FF1, MG, DI, DM, DM, 0, DI, 0, DI, 0, b1, 1, 1, 0, 1);
    launchG<128,1,0,1>(FF1, w2, FF2, MG, DM, DI, DI, 0, DM, 0, DM, 0, b2, 0, 1);
    ln_res<<<MG, T>>>(FF2, ATTG, fls, flb, out + (long)MH * DM);
}